// round 4
// baseline (speedup 1.0000x reference)
#include <cuda_runtime.h>
#include <cuda_bf16.h>
#include <cstdint>
#include <math.h>

#define SEQ 2048
#define DIM 1024
#define NHEADS 8
#define HD 128
#define LOG2E 1.4426950408889634f
#define INV_TAU 0.088388347648318447f

// ---------------- scratch (device globals; no allocation) ----------------
__device__ float g_itilde[NHEADS * SEQ];
__device__ float g_logsig[NHEADS * SEQ];
__device__ float g_a2[NHEADS * SEQ];      // a_j * log2(e)
__device__ float g_M2[NHEADS * SEQ];      // M_i * log2(e)
__device__ float g_nfloor[NHEADS * SEQ];  // exp(-(csum_i + M_i))
__device__ float g_Opart[2][SEQ * DIM];   // partial O per column-parity
__device__ float g_bpart[2][NHEADS * SEQ];

// ---------------- smem layout (bytes). Row pitch = 136 bf16 = 272 B ----------------
#define PITCH 272
#define OFF_QHI 0          /* 128 x 272 = 34816 */
#define OFF_QLO 34816
#define KV_BASE 69632      /* two stage blocks of 4 x (64 x 272) = 69632 each */
#define KV_STRIDE 69632
#define KO_HI 0
#define KO_LO 17408
#define VO_HI 34816
#define VO_LO 52224
#define OFF_EA (KV_BASE + 2 * KV_STRIDE) /* 2 x 68 floats (per stage) */
#define EA_STRIDE_F 68
#define SMEM_TOTAL (OFF_EA + 2 * 272)

// ---------------- helpers ----------------
__device__ __forceinline__ uint32_t smem_u32(const void* p) {
    uint32_t a;
    asm("{ .reg .u64 t; cvta.to.shared.u64 t, %1; cvt.u32.u64 %0, t; }" : "=r"(a) : "l"(p));
    return a;
}
__device__ __forceinline__ void ldsm4(uint32_t* r, uint32_t addr) {
    asm volatile("ldmatrix.sync.aligned.m8n8.x4.shared.b16 {%0,%1,%2,%3}, [%4];"
                 : "=r"(r[0]), "=r"(r[1]), "=r"(r[2]), "=r"(r[3]) : "r"(addr));
}
__device__ __forceinline__ void ldsm4t(uint32_t* r, uint32_t addr) {
    asm volatile("ldmatrix.sync.aligned.m8n8.x4.trans.shared.b16 {%0,%1,%2,%3}, [%4];"
                 : "=r"(r[0]), "=r"(r[1]), "=r"(r[2]), "=r"(r[3]) : "r"(addr));
}
__device__ __forceinline__ void mma16816(float* d, const uint32_t* a, const uint32_t* b) {
    asm volatile(
        "mma.sync.aligned.m16n8k16.row.col.f32.bf16.bf16.f32 "
        "{%0,%1,%2,%3}, {%4,%5,%6,%7}, {%8,%9}, {%0,%1,%2,%3};"
        : "+f"(d[0]), "+f"(d[1]), "+f"(d[2]), "+f"(d[3])
        : "r"(a[0]), "r"(a[1]), "r"(a[2]), "r"(a[3]), "r"(b[0]), "r"(b[1]));
}
__device__ __forceinline__ uint32_t pack_bf2(float a, float b) {
    __nv_bfloat162 t = __floats2bfloat162_rn(a, b);
    return *reinterpret_cast<uint32_t*>(&t);
}
__device__ __forceinline__ float bf_hi(float f) {
    return __bfloat162float(__float2bfloat16(f));
}

// ---------------- kernel A: gate projections (verified) ----------------
__global__ void gates_kernel(const float* __restrict__ q, const float* __restrict__ k,
                             const float* __restrict__ v,
                             const float* __restrict__ Wi_w, const float* __restrict__ Wi_b,
                             const float* __restrict__ Wf_w, const float* __restrict__ Wf_b) {
    const int s = blockIdx.x;
    const int h = threadIdx.x >> 5;
    const int lane = threadIdx.x & 31;
    const float* wi = Wi_w + h * 3 * DIM;
    const float* wf = Wf_w + h * 3 * DIM;
    const float* qr = q + (size_t)s * DIM;
    const float* kr = k + (size_t)s * DIM;
    const float* vr = v + (size_t)s * DIM;

    float si = 0.f, sf = 0.f;
#pragma unroll
    for (int m = 0; m < 8; m++) {
        const int d = m * 128 + lane * 4;
        const float4 xq = *reinterpret_cast<const float4*>(qr + d);
        const float4 xk = *reinterpret_cast<const float4*>(kr + d);
        const float4 xv = *reinterpret_cast<const float4*>(vr + d);
        float4 w0 = *reinterpret_cast<const float4*>(wi + d);
        float4 w1 = *reinterpret_cast<const float4*>(wi + DIM + d);
        float4 w2 = *reinterpret_cast<const float4*>(wi + 2 * DIM + d);
        si += xq.x * w0.x + xq.y * w0.y + xq.z * w0.z + xq.w * w0.w;
        si += xk.x * w1.x + xk.y * w1.y + xk.z * w1.z + xk.w * w1.w;
        si += xv.x * w2.x + xv.y * w2.y + xv.z * w2.z + xv.w * w2.w;
        w0 = *reinterpret_cast<const float4*>(wf + d);
        w1 = *reinterpret_cast<const float4*>(wf + DIM + d);
        w2 = *reinterpret_cast<const float4*>(wf + 2 * DIM + d);
        sf += xq.x * w0.x + xq.y * w0.y + xq.z * w0.z + xq.w * w0.w;
        sf += xk.x * w1.x + xk.y * w1.y + xk.z * w1.z + xk.w * w1.w;
        sf += xv.x * w2.x + xv.y * w2.y + xv.z * w2.z + xv.w * w2.w;
    }
#pragma unroll
    for (int o = 16; o; o >>= 1) {
        si += __shfl_xor_sync(0xffffffffu, si, o);
        sf += __shfl_xor_sync(0xffffffffu, sf, o);
    }
    if (lane == 0) {
        g_itilde[h * SEQ + s] = si + Wi_b[h];
        const float ft = sf + Wf_b[h];
        g_logsig[h * SEQ + s] = fminf(ft, 0.f) - log1pf(__expf(-fabsf(ft)));
    }
}

// ---------------- kernel B: per-head scans (verified) ----------------
__global__ void scan_kernel() {
    const int h = blockIdx.x;
    const int t = threadIdx.x;
    __shared__ float sc[256];

    float cs[8];
    float run = 0.f;
#pragma unroll
    for (int m = 0; m < 8; m++) {
        run += g_logsig[h * SEQ + t * 8 + m];
        cs[m] = run;
    }
    sc[t] = run;
    __syncthreads();
#pragma unroll
    for (int off = 1; off < 256; off <<= 1) {
        const float vv = sc[t];
        const float uu = (t >= off) ? sc[t - off] : 0.f;
        __syncthreads();
        sc[t] = vv + uu;
        __syncthreads();
    }
    const float base = (t == 0) ? 0.f : sc[t - 1];

    float a[8], amax[8], csum[8];
    float runm = -3.402823466e38f;
#pragma unroll
    for (int m = 0; m < 8; m++) {
        csum[m] = base + cs[m];
        a[m] = g_itilde[h * SEQ + t * 8 + m] - csum[m];
        runm = fmaxf(runm, a[m]);
        amax[m] = runm;
    }
    __syncthreads();
    sc[t] = runm;
    __syncthreads();
#pragma unroll
    for (int off = 1; off < 256; off <<= 1) {
        const float vv = sc[t];
        const float uu = (t >= off) ? sc[t - off] : -3.402823466e38f;
        __syncthreads();
        sc[t] = fmaxf(vv, uu);
        __syncthreads();
    }
    const float mbase = (t == 0) ? -3.402823466e38f : sc[t - 1];

#pragma unroll
    for (int m = 0; m < 8; m++) {
        const int j = h * SEQ + t * 8 + m;
        const float Mv = fmaxf(mbase, amax[m]);
        g_a2[j] = a[m] * LOG2E;
        g_M2[j] = Mv * LOG2E;
        g_nfloor[j] = exp2f(-(csum[m] + Mv) * LOG2E);
    }
}

// stage one K/V column tile (64 rows) into stage block `kvb` (byte offset)
__device__ __forceinline__ void stage_kv(char* smraw, float* smf,
                                         const float* __restrict__ k,
                                         const float* __restrict__ v,
                                         int j0, int h, int hb, uint32_t kvb,
                                         int eaF, int tid) {
#pragma unroll 2
    for (int idx = tid; idx < 64 * 32; idx += 256) {
        const int r = idx >> 5, c4 = (idx & 31) * 4;
        const float4 f = *reinterpret_cast<const float4*>(k + (size_t)(j0 + r) * DIM + h * HD + c4);
        const float hx = bf_hi(f.x), hy = bf_hi(f.y), hz = bf_hi(f.z), hw = bf_hi(f.w);
        char* bp = smraw + kvb + KO_HI + r * PITCH + c4 * 2;
        *reinterpret_cast<uint32_t*>(bp) = pack_bf2(hx, hy);
        *reinterpret_cast<uint32_t*>(bp + 4) = pack_bf2(hz, hw);
        char* lp = bp + (KO_LO - KO_HI);
        *reinterpret_cast<uint32_t*>(lp) = pack_bf2(f.x - hx, f.y - hy);
        *reinterpret_cast<uint32_t*>(lp + 4) = pack_bf2(f.z - hz, f.w - hw);

        const float4 g = *reinterpret_cast<const float4*>(v + (size_t)(j0 + r) * DIM + h * HD + c4);
        const float gx = bf_hi(g.x), gy = bf_hi(g.y), gz = bf_hi(g.z), gw = bf_hi(g.w);
        char* vp = smraw + kvb + VO_HI + r * PITCH + c4 * 2;
        *reinterpret_cast<uint32_t*>(vp) = pack_bf2(gx, gy);
        *reinterpret_cast<uint32_t*>(vp + 4) = pack_bf2(gz, gw);
        char* wp = vp + (VO_LO - VO_HI);
        *reinterpret_cast<uint32_t*>(wp) = pack_bf2(g.x - gx, g.y - gy);
        *reinterpret_cast<uint32_t*>(wp + 4) = pack_bf2(g.z - gz, g.w - gw);
    }
    if (tid < 64) smf[eaF + tid] = exp2f(g_a2[hb + j0 + tid] - g_M2[hb + j0 + 63]);
    if (tid == 64) smf[eaF + 64] = g_M2[hb + j0 + 63];
}

// ---------------- main kernel: HMMA flash mLSTM, double-buffered ----------------
__global__ void __launch_bounds__(256, 1)
mlstm_mma(const float* __restrict__ q, const float* __restrict__ k,
          const float* __restrict__ v) {
    extern __shared__ char smraw[];
    const uint32_t sb = smem_u32(smraw);
    float* smf = reinterpret_cast<float*>(smraw);

    const int tid = threadIdx.x;
    const int lane = tid & 31;
    const int warp = tid >> 5;
    const int qc = lane & 3;
    const int h = blockIdx.y, hb = h * SEQ;
    const int p = blockIdx.x >> 1, par = blockIdx.x & 1;
    const int m0 = warp * 16;

    const uint32_t offA = (uint32_t)(m0 + (lane & 15)) * PITCH + ((lane >> 4) * 8) * 2;
    const uint32_t offB = (uint32_t)(((lane >> 4) & 1) * 8 + (lane & 7)) * PITCH +
                          (((lane >> 3) & 1) * 8) * 2;
    const uint32_t offV = (uint32_t)(lane & 15) * PITCH + ((lane >> 4) * 8) * 2;

    for (int hs = 0; hs < 2; hs++) {
        const int rtc = hs ? (15 - p) : p;
        const int i0 = rtc * 128;
        const int n_ct = 2 * rtc + 2;

        // --- stage Q hi/lo (scaled by 1/tau) + prime first K/V tile ---
#pragma unroll 2
        for (int idx = tid; idx < 128 * 32; idx += 256) {
            const int r = idx >> 5, c4 = (idx & 31) * 4;
            float4 f = *reinterpret_cast<const float4*>(q + (size_t)(i0 + r) * DIM + h * HD + c4);
            f.x *= INV_TAU; f.y *= INV_TAU; f.z *= INV_TAU; f.w *= INV_TAU;
            const float hx = bf_hi(f.x), hy = bf_hi(f.y), hz = bf_hi(f.z), hw = bf_hi(f.w);
            char* bp = smraw + OFF_QHI + r * PITCH + c4 * 2;
            *reinterpret_cast<uint32_t*>(bp) = pack_bf2(hx, hy);
            *reinterpret_cast<uint32_t*>(bp + 4) = pack_bf2(hz, hw);
            char* lp = bp + (OFF_QLO - OFF_QHI);
            *reinterpret_cast<uint32_t*>(lp) = pack_bf2(f.x - hx, f.y - hy);
            *reinterpret_cast<uint32_t*>(lp + 4) = pack_bf2(f.z - hz, f.w - hw);
        }
        stage_kv(smraw, smf, k, v, par * 64, h, hb, KV_BASE, OFF_EA / 4, tid);
        __syncthreads();

        const int r_lo = i0 + m0 + (lane >> 2);
        const int r_hi = r_lo + 8;
        const float m2_lo = g_M2[hb + r_lo];
        const float m2_hi = g_M2[hb + r_hi];

        float accO[16][4];
#pragma unroll
        for (int a = 0; a < 16; a++)
#pragma unroll
            for (int b = 0; b < 4; b++) accO[a][b] = 0.f;
        float bsl = 0.f, bsh = 0.f;

        for (int ct = par, it = 0; ct < n_ct; ct += 2, it++) {
            const int j0 = ct * 64;
            const uint32_t kvb = KV_BASE + (uint32_t)(it & 1) * KV_STRIDE;
            const int eaF = OFF_EA / 4 + (it & 1) * EA_STRIDE_F;

            // issue next tile's staging into the other buffer (overlaps compute)
            if (ct + 2 < n_ct)
                stage_kv(smraw, smf, k, v, (ct + 2) * 64, h, hb,
                         KV_BASE + (uint32_t)((it + 1) & 1) * KV_STRIDE,
                         OFF_EA / 4 + ((it + 1) & 1) * EA_STRIDE_F, tid);

            // fully-masked warp-tiles: last (odd) col-tile, rows < j0
            const bool fskip = (ct == 2 * rtc + 1) && (warp < 4);
            if (!fskip) {
                // --- GEMM1: S = Q K^T (3-pass bf16 split) ---
                float accS[8][4];
#pragma unroll
                for (int a = 0; a < 8; a++)
#pragma unroll
                    for (int b = 0; b < 4; b++) accS[a][b] = 0.f;

#pragma unroll
                for (int kt = 0; kt < 8; kt++) {
                    uint32_t ah[4], al[4];
                    const uint32_t aaddr = sb + OFF_QHI + offA + kt * 32;
                    ldsm4(ah, aaddr);
                    ldsm4(al, aaddr + (OFF_QLO - OFF_QHI));
#pragma unroll
                    for (int np = 0; np < 4; np++) {
                        const uint32_t baddr = sb + kvb + KO_HI + offB + np * (16 * PITCH) + kt * 32;
                        uint32_t bh4[4], bl4[4];
                        ldsm4(bh4, baddr);
                        mma16816(accS[2 * np], ah, bh4);
                        mma16816(accS[2 * np + 1], ah, bh4 + 2);
                        ldsm4(bl4, baddr + (KO_LO - KO_HI));
                        mma16816(accS[2 * np], ah, bl4);
                        mma16816(accS[2 * np + 1], ah, bl4 + 2);
                        mma16816(accS[2 * np], al, bh4);
                        mma16816(accS[2 * np + 1], al, bh4 + 2);
                    }
                }

                // --- decay weights + causal mask + rowsum ---
                const float ref2 = smf[eaF + 64];
                const float em_lo = exp2f(ref2 - m2_lo);
                const float em_hi = exp2f(ref2 - m2_hi);
                const bool diag = (ct >= 2 * rtc);
#pragma unroll
                for (int nt = 0; nt < 8; nt++) {
                    const int col0 = nt * 8 + 2 * qc;
                    const float w0 = smf[eaF + col0], w1 = smf[eaF + col0 + 1];
                    float* c = accS[nt];
                    float p00 = c[0] * w0 * em_lo, p01 = c[1] * w1 * em_lo;
                    float p10 = c[2] * w0 * em_hi, p11 = c[3] * w1 * em_hi;
                    if (diag) {
                        const int jc = j0 + col0;
                        if (jc > r_lo) p00 = 0.f;
                        if (jc + 1 > r_lo) p01 = 0.f;
                        if (jc > r_hi) p10 = 0.f;
                        if (jc + 1 > r_hi) p11 = 0.f;
                    }
                    bsl += p00 + p01;
                    bsh += p10 + p11;
                    c[0] = p00; c[1] = p01; c[2] = p10; c[3] = p11;
                }

                // --- GEMM2: O += P V (P from registers, 3-pass bf16 split) ---
#pragma unroll
                for (int kt2 = 0; kt2 < 4; kt2++) {
                    const float* s0 = accS[2 * kt2];
                    const float* s1 = accS[2 * kt2 + 1];
                    const float h00 = bf_hi(s0[0]), h01 = bf_hi(s0[1]);
                    const float h02 = bf_hi(s0[2]), h03 = bf_hi(s0[3]);
                    const float h10 = bf_hi(s1[0]), h11 = bf_hi(s1[1]);
                    const float h12 = bf_hi(s1[2]), h13 = bf_hi(s1[3]);
                    uint32_t ph[4], pl[4];
                    ph[0] = pack_bf2(h00, h01);
                    ph[1] = pack_bf2(h02, h03);
                    ph[2] = pack_bf2(h10, h11);
                    ph[3] = pack_bf2(h12, h13);
                    pl[0] = pack_bf2(s0[0] - h00, s0[1] - h01);
                    pl[1] = pack_bf2(s0[2] - h02, s0[3] - h03);
                    pl[2] = pack_bf2(s1[0] - h10, s1[1] - h11);
                    pl[3] = pack_bf2(s1[2] - h12, s1[3] - h13);
#pragma unroll
                    for (int dp = 0; dp < 8; dp++) {
                        const uint32_t vaddr = sb + kvb + VO_HI + offV + kt2 * (16 * PITCH) + dp * 32;
                        uint32_t vh4[4], vl4[4];
                        ldsm4t(vh4, vaddr);
                        mma16816(accO[2 * dp], ph, vh4);
                        mma16816(accO[2 * dp + 1], ph, vh4 + 2);
                        ldsm4t(vl4, vaddr + (VO_LO - VO_HI));
                        mma16816(accO[2 * dp], ph, vl4);
                        mma16816(accO[2 * dp + 1], ph, vl4 + 2);
                        mma16816(accO[2 * dp], pl, vh4);
                        mma16816(accO[2 * dp + 1], pl, vh4 + 2);
                    }
                }
            }
            __syncthreads();  // next buffer staged AND current buffer reads done
        }

        // --- reduce rowsums across quad, store partials ---
        bsl += __shfl_xor_sync(0xffffffffu, bsl, 1);
        bsl += __shfl_xor_sync(0xffffffffu, bsl, 2);
        bsh += __shfl_xor_sync(0xffffffffu, bsh, 1);
        bsh += __shfl_xor_sync(0xffffffffu, bsh, 2);
        if (qc == 0) {
            g_bpart[par][hb + r_lo] = bsl;
            g_bpart[par][hb + r_hi] = bsh;
        }
        float* od = g_Opart[par];
#pragma unroll
        for (int dt = 0; dt < 16; dt++) {
            const int col = h * HD + dt * 8 + 2 * qc;
            *reinterpret_cast<float2*>(od + (size_t)r_lo * DIM + col) =
                make_float2(accO[dt][0], accO[dt][1]);
            *reinterpret_cast<float2*>(od + (size_t)r_hi * DIM + col) =
                make_float2(accO[dt][2], accO[dt][3]);
        }
        __syncthreads();  // all reads of Q/KV buffers done before next half restages
    }
}

// ---------------- merge + denominator + GroupNorm ----------------
__global__ void merge_gn(float* __restrict__ out, const float* __restrict__ gn_w,
                         const float* __restrict__ gn_b) {
    const int s = blockIdx.x;
    const int h = threadIdx.x >> 5;
    const int lane = threadIdx.x & 31;
    const size_t off = (size_t)s * DIM + h * HD + lane * 4;

    const float4 a = *reinterpret_cast<const float4*>(g_Opart[0] + off);
    const float4 b4 = *reinterpret_cast<const float4*>(g_Opart[1] + off);
    const float bs = g_bpart[0][h * SEQ + s] + g_bpart[1][h * SEQ + s];
    const float inv = 1.0f / (fmaxf(fabsf(bs), g_nfloor[h * SEQ + s]) + 1e-6f);

    float4 x;
    x.x = (a.x + b4.x) * inv;
    x.y = (a.y + b4.y) * inv;
    x.z = (a.z + b4.z) * inv;
    x.w = (a.w + b4.w) * inv;

    float sum = x.x + x.y + x.z + x.w;
#pragma unroll
    for (int o = 16; o; o >>= 1) sum += __shfl_xor_sync(0xffffffffu, sum, o);
    const float mean = sum * (1.0f / 128.0f);
    const float d0 = x.x - mean, d1 = x.y - mean, d2 = x.z - mean, d3 = x.w - mean;
    float sq = d0 * d0 + d1 * d1 + d2 * d2 + d3 * d3;
#pragma unroll
    for (int o = 16; o; o >>= 1) sq += __shfl_xor_sync(0xffffffffu, sq, o);
    const float istd = rsqrtf(sq * (1.0f / 128.0f) + 1e-5f);

    const float4 w = *reinterpret_cast<const float4*>(gn_w + h * HD + lane * 4);
    const float4 bb = *reinterpret_cast<const float4*>(gn_b + h * HD + lane * 4);
    float4 y;
    y.x = d0 * istd * w.x + bb.x;
    y.y = d1 * istd * w.y + bb.y;
    y.z = d2 * istd * w.z + bb.z;
    y.w = d3 * istd * w.w + bb.w;
    *reinterpret_cast<float4*>(out + off) = y;
}

// ---------------- launch ----------------
extern "C" void kernel_launch(void* const* d_in, const int* in_sizes, int n_in,
                              void* d_out, int out_size) {
    const float* q = (const float*)d_in[0];
    const float* k = (const float*)d_in[1];
    const float* v = (const float*)d_in[2];
    const float* Wi_w = (const float*)d_in[3];
    const float* Wi_b = (const float*)d_in[4];
    const float* Wf_w = (const float*)d_in[5];
    const float* Wf_b = (const float*)d_in[6];
    const float* gn_w = (const float*)d_in[7];
    const float* gn_b = (const float*)d_in[8];
    float* out = (float*)d_out;

    gates_kernel<<<SEQ, 256>>>(q, k, v, Wi_w, Wi_b, Wf_w, Wf_b);
    scan_kernel<<<NHEADS, 256>>>();

    cudaFuncSetAttribute(mlstm_mma, cudaFuncAttributeMaxDynamicSharedMemorySize, SMEM_TOTAL);
    dim3 grid(16, NHEADS);
    mlstm_mma<<<grid, 256, SMEM_TOTAL>>>(q, k, v);

    merge_gn<<<SEQ, 256>>>(out, gn_w, gn_b);
}

// round 6
// speedup vs baseline: 1.0336x; 1.0336x over previous
#include <cuda_runtime.h>
#include <cuda_bf16.h>
#include <cstdint>
#include <math.h>

#define SEQ 2048
#define DIM 1024
#define NHEADS 8
#define HD 128
#define LOG2E 1.4426950408889634f
#define INV_TAU 0.088388347648318447f

// ---------------- scratch (device globals; no allocation) ----------------
__device__ float g_itilde[NHEADS * SEQ];
__device__ float g_logsig[NHEADS * SEQ];
__device__ float g_a2[NHEADS * SEQ];      // a_j * log2(e)
__device__ float g_M2[NHEADS * SEQ];      // M_i * log2(e)
__device__ float g_nfloor[NHEADS * SEQ];  // exp(-(csum_i + M_i))
__device__ float g_Opart[2][SEQ * DIM];   // partial O per column-parity
__device__ float g_bpart[2][NHEADS * SEQ];

// ---------------- smem layout (bytes). Row pitch = 136 bf16 = 272 B ----------------
#define PITCH 272
#define OFF_QHI 0          /* 128 x 272 = 34816 */
#define OFF_QLO 34816
#define OFF_KHI 69632      /* 64 x 272 = 17408 each */
#define OFF_KLO 87040
#define OFF_VHI 104448
#define OFF_VLO 121856
#define OFF_EA 139264      /* 68 floats */
#define EAF (OFF_EA / 4)
#define SMEM_TOTAL (OFF_EA + 272)

// ---------------- helpers ----------------
__device__ __forceinline__ uint32_t smem_u32(const void* p) {
    uint32_t a;
    asm("{ .reg .u64 t; cvta.to.shared.u64 t, %1; cvt.u32.u64 %0, t; }" : "=r"(a) : "l"(p));
    return a;
}
__device__ __forceinline__ void ldsm4(uint32_t* r, uint32_t addr) {
    asm volatile("ldmatrix.sync.aligned.m8n8.x4.shared.b16 {%0,%1,%2,%3}, [%4];"
                 : "=r"(r[0]), "=r"(r[1]), "=r"(r[2]), "=r"(r[3]) : "r"(addr));
}
__device__ __forceinline__ void ldsm4t(uint32_t* r, uint32_t addr) {
    asm volatile("ldmatrix.sync.aligned.m8n8.x4.trans.shared.b16 {%0,%1,%2,%3}, [%4];"
                 : "=r"(r[0]), "=r"(r[1]), "=r"(r[2]), "=r"(r[3]) : "r"(addr));
}
__device__ __forceinline__ void mma16816(float* d, const uint32_t* a, const uint32_t* b) {
    asm volatile(
        "mma.sync.aligned.m16n8k16.row.col.f32.bf16.bf16.f32 "
        "{%0,%1,%2,%3}, {%4,%5,%6,%7}, {%8,%9}, {%0,%1,%2,%3};"
        : "+f"(d[0]), "+f"(d[1]), "+f"(d[2]), "+f"(d[3])
        : "r"(a[0]), "r"(a[1]), "r"(a[2]), "r"(a[3]), "r"(b[0]), "r"(b[1]));
}
__device__ __forceinline__ uint32_t pack_bf2(float a, float b) {
    __nv_bfloat162 t = __floats2bfloat162_rn(a, b);
    return *reinterpret_cast<uint32_t*>(&t);
}
__device__ __forceinline__ float bf_hi(float f) {
    return __bfloat162float(__float2bfloat16(f));
}

// ---------------- kernel A: gate projections (verified) ----------------
__global__ void gates_kernel(const float* __restrict__ q, const float* __restrict__ k,
                             const float* __restrict__ v,
                             const float* __restrict__ Wi_w, const float* __restrict__ Wi_b,
                             const float* __restrict__ Wf_w, const float* __restrict__ Wf_b) {
    const int s = blockIdx.x;
    const int h = threadIdx.x >> 5;
    const int lane = threadIdx.x & 31;
    const float* wi = Wi_w + h * 3 * DIM;
    const float* wf = Wf_w + h * 3 * DIM;
    const float* qr = q + (size_t)s * DIM;
    const float* kr = k + (size_t)s * DIM;
    const float* vr = v + (size_t)s * DIM;

    float si = 0.f, sf = 0.f;
#pragma unroll
    for (int m = 0; m < 8; m++) {
        const int d = m * 128 + lane * 4;
        const float4 xq = *reinterpret_cast<const float4*>(qr + d);
        const float4 xk = *reinterpret_cast<const float4*>(kr + d);
        const float4 xv = *reinterpret_cast<const float4*>(vr + d);
        float4 w0 = *reinterpret_cast<const float4*>(wi + d);
        float4 w1 = *reinterpret_cast<const float4*>(wi + DIM + d);
        float4 w2 = *reinterpret_cast<const float4*>(wi + 2 * DIM + d);
        si += xq.x * w0.x + xq.y * w0.y + xq.z * w0.z + xq.w * w0.w;
        si += xk.x * w1.x + xk.y * w1.y + xk.z * w1.z + xk.w * w1.w;
        si += xv.x * w2.x + xv.y * w2.y + xv.z * w2.z + xv.w * w2.w;
        w0 = *reinterpret_cast<const float4*>(wf + d);
        w1 = *reinterpret_cast<const float4*>(wf + DIM + d);
        w2 = *reinterpret_cast<const float4*>(wf + 2 * DIM + d);
        sf += xq.x * w0.x + xq.y * w0.y + xq.z * w0.z + xq.w * w0.w;
        sf += xk.x * w1.x + xk.y * w1.y + xk.z * w1.z + xk.w * w1.w;
        sf += xv.x * w2.x + xv.y * w2.y + xv.z * w2.z + xv.w * w2.w;
    }
#pragma unroll
    for (int o = 16; o; o >>= 1) {
        si += __shfl_xor_sync(0xffffffffu, si, o);
        sf += __shfl_xor_sync(0xffffffffu, sf, o);
    }
    if (lane == 0) {
        g_itilde[h * SEQ + s] = si + Wi_b[h];
        const float ft = sf + Wf_b[h];
        g_logsig[h * SEQ + s] = fminf(ft, 0.f) - log1pf(__expf(-fabsf(ft)));
    }
}

// ---------------- kernel B: per-head scans (verified) ----------------
__global__ void scan_kernel() {
    const int h = blockIdx.x;
    const int t = threadIdx.x;
    __shared__ float sc[256];

    float cs[8];
    float run = 0.f;
#pragma unroll
    for (int m = 0; m < 8; m++) {
        run += g_logsig[h * SEQ + t * 8 + m];
        cs[m] = run;
    }
    sc[t] = run;
    __syncthreads();
#pragma unroll
    for (int off = 1; off < 256; off <<= 1) {
        const float vv = sc[t];
        const float uu = (t >= off) ? sc[t - off] : 0.f;
        __syncthreads();
        sc[t] = vv + uu;
        __syncthreads();
    }
    const float base = (t == 0) ? 0.f : sc[t - 1];

    float a[8], amax[8], csum[8];
    float runm = -3.402823466e38f;
#pragma unroll
    for (int m = 0; m < 8; m++) {
        csum[m] = base + cs[m];
        a[m] = g_itilde[h * SEQ + t * 8 + m] - csum[m];
        runm = fmaxf(runm, a[m]);
        amax[m] = runm;
    }
    __syncthreads();
    sc[t] = runm;
    __syncthreads();
#pragma unroll
    for (int off = 1; off < 256; off <<= 1) {
        const float vv = sc[t];
        const float uu = (t >= off) ? sc[t - off] : -3.402823466e38f;
        __syncthreads();
        sc[t] = fmaxf(vv, uu);
        __syncthreads();
    }
    const float mbase = (t == 0) ? -3.402823466e38f : sc[t - 1];

#pragma unroll
    for (int m = 0; m < 8; m++) {
        const int j = h * SEQ + t * 8 + m;
        const float Mv = fmaxf(mbase, amax[m]);
        g_a2[j] = a[m] * LOG2E;
        g_M2[j] = Mv * LOG2E;
        g_nfloor[j] = exp2f(-(csum[m] + Mv) * LOG2E);
    }
}

// ---------------- main kernel: HMMA flash mLSTM (interleaved accumulators) ----------------
// grid (16, 8): blockIdx.x = pair p (>>1) + column parity (&1); blockIdx.y = head.
__global__ void __launch_bounds__(256, 1)
mlstm_mma(const float* __restrict__ q, const float* __restrict__ k,
          const float* __restrict__ v) {
    extern __shared__ char smraw[];
    const uint32_t sb = smem_u32(smraw);
    float* smf = reinterpret_cast<float*>(smraw);

    const int tid = threadIdx.x;
    const int lane = tid & 31;
    const int warp = tid >> 5;
    const int qc = lane & 3;
    const int h = blockIdx.y, hb = h * SEQ;
    const int p = blockIdx.x >> 1, par = blockIdx.x & 1;
    const int m0 = warp * 16;

    const uint32_t offA = (uint32_t)(m0 + (lane & 15)) * PITCH + ((lane >> 4) * 8) * 2;
    const uint32_t offB = (uint32_t)(((lane >> 4) & 1) * 8 + (lane & 7)) * PITCH +
                          (((lane >> 3) & 1) * 8) * 2;
    const uint32_t offV = (uint32_t)(lane & 15) * PITCH + ((lane >> 4) * 8) * 2;

    for (int hs = 0; hs < 2; hs++) {
        const int rtc = hs ? (15 - p) : p;
        const int i0 = rtc * 128;
        __syncthreads();  // previous half finished reading Q

        // --- stage Q hi/lo (scaled by 1/tau) ---
        for (int idx = tid; idx < 128 * 32; idx += 256) {
            const int r = idx >> 5, c4 = (idx & 31) * 4;
            float4 f = *reinterpret_cast<const float4*>(q + (size_t)(i0 + r) * DIM + h * HD + c4);
            f.x *= INV_TAU; f.y *= INV_TAU; f.z *= INV_TAU; f.w *= INV_TAU;
            const float hx = bf_hi(f.x), hy = bf_hi(f.y), hz = bf_hi(f.z), hw = bf_hi(f.w);
            char* bp = smraw + OFF_QHI + r * PITCH + c4 * 2;
            *reinterpret_cast<uint32_t*>(bp) = pack_bf2(hx, hy);
            *reinterpret_cast<uint32_t*>(bp + 4) = pack_bf2(hz, hw);
            char* lp = bp + (OFF_QLO - OFF_QHI);
            *reinterpret_cast<uint32_t*>(lp) = pack_bf2(f.x - hx, f.y - hy);
            *reinterpret_cast<uint32_t*>(lp + 4) = pack_bf2(f.z - hz, f.w - hw);
        }

        const int r_lo = i0 + m0 + (lane >> 2);
        const int r_hi = r_lo + 8;
        const float m2_lo = g_M2[hb + r_lo];
        const float m2_hi = g_M2[hb + r_hi];

        float accO[16][4];
#pragma unroll
        for (int a = 0; a < 16; a++)
#pragma unroll
            for (int b = 0; b < 4; b++) accO[a][b] = 0.f;
        float bsl = 0.f, bsh = 0.f;

        const int n_ct = 2 * rtc + 2;
        for (int ct = par; ct < n_ct; ct += 2) {
            const int j0 = ct * 64;
            __syncthreads();  // previous tile done reading K/V

            // --- stage K and V hi/lo ---
            for (int idx = tid; idx < 64 * 32; idx += 256) {
                const int r = idx >> 5, c4 = (idx & 31) * 4;
                const float4 f = *reinterpret_cast<const float4*>(k + (size_t)(j0 + r) * DIM + h * HD + c4);
                const float hx = bf_hi(f.x), hy = bf_hi(f.y), hz = bf_hi(f.z), hw = bf_hi(f.w);
                char* bp = smraw + OFF_KHI + r * PITCH + c4 * 2;
                *reinterpret_cast<uint32_t*>(bp) = pack_bf2(hx, hy);
                *reinterpret_cast<uint32_t*>(bp + 4) = pack_bf2(hz, hw);
                char* lp = bp + (OFF_KLO - OFF_KHI);
                *reinterpret_cast<uint32_t*>(lp) = pack_bf2(f.x - hx, f.y - hy);
                *reinterpret_cast<uint32_t*>(lp + 4) = pack_bf2(f.z - hz, f.w - hw);

                const float4 g = *reinterpret_cast<const float4*>(v + (size_t)(j0 + r) * DIM + h * HD + c4);
                const float gx = bf_hi(g.x), gy = bf_hi(g.y), gz = bf_hi(g.z), gw = bf_hi(g.w);
                char* vp = smraw + OFF_VHI + r * PITCH + c4 * 2;
                *reinterpret_cast<uint32_t*>(vp) = pack_bf2(gx, gy);
                *reinterpret_cast<uint32_t*>(vp + 4) = pack_bf2(gz, gw);
                char* wp = vp + (OFF_VLO - OFF_VHI);
                *reinterpret_cast<uint32_t*>(wp) = pack_bf2(g.x - gx, g.y - gy);
                *reinterpret_cast<uint32_t*>(wp + 4) = pack_bf2(g.z - gz, g.w - gw);
            }
            if (tid < 64) smf[EAF + tid] = exp2f(g_a2[hb + j0 + tid] - g_M2[hb + j0 + 63]);
            if (tid == 64) smf[EAF + 64] = g_M2[hb + j0 + 63];
            __syncthreads();

            // fully-masked warp-tiles: last (odd) col-tile, rows < j0
            const bool fskip = (ct == 2 * rtc + 1) && (warp < 4);
            if (fskip) continue;

            // --- GEMM1: S = Q K^T (3-pass bf16 split, accumulators interleaved) ---
            float accS[8][4];
#pragma unroll
            for (int a = 0; a < 8; a++)
#pragma unroll
                for (int b = 0; b < 4; b++) accS[a][b] = 0.f;

#pragma unroll
            for (int kt = 0; kt < 8; kt++) {
                uint32_t ah[4], al[4];
                const uint32_t aaddr = sb + OFF_QHI + offA + kt * 32;
                ldsm4(ah, aaddr);
                ldsm4(al, aaddr + (OFF_QLO - OFF_QHI));
#pragma unroll
                for (int np2 = 0; np2 < 2; np2++) {
                    const uint32_t b0a = sb + OFF_KHI + offB + (2 * np2) * (16 * PITCH) + kt * 32;
                    const uint32_t b1a = b0a + 16 * PITCH;
                    uint32_t bh0[4], bl0[4], bh1[4], bl1[4];
                    ldsm4(bh0, b0a);
                    ldsm4(bh1, b1a);
                    ldsm4(bl0, b0a + (OFF_KLO - OFF_KHI));
                    ldsm4(bl1, b1a + (OFF_KLO - OFF_KHI));
                    float* a0 = accS[4 * np2];
                    float* a1 = accS[4 * np2 + 1];
                    float* a2 = accS[4 * np2 + 2];
                    float* a3 = accS[4 * np2 + 3];
                    mma16816(a0, ah, bh0); mma16816(a2, ah, bh1);
                    mma16816(a1, ah, bh0 + 2); mma16816(a3, ah, bh1 + 2);
                    mma16816(a0, ah, bl0); mma16816(a2, ah, bl1);
                    mma16816(a1, ah, bl0 + 2); mma16816(a3, ah, bl1 + 2);
                    mma16816(a0, al, bh0); mma16816(a2, al, bh1);
                    mma16816(a1, al, bh0 + 2); mma16816(a3, al, bh1 + 2);
                }
            }

            // --- decay weights + causal mask + rowsum ---
            const float ref2 = smf[EAF + 64];
            const float em_lo = exp2f(ref2 - m2_lo);
            const float em_hi = exp2f(ref2 - m2_hi);
            const bool diag = (ct >= 2 * rtc);
#pragma unroll
            for (int nt = 0; nt < 8; nt++) {
                const int col0 = nt * 8 + 2 * qc;
                const float w0 = smf[EAF + col0], w1 = smf[EAF + col0 + 1];
                float* c = accS[nt];
                float p00 = c[0] * w0 * em_lo, p01 = c[1] * w1 * em_lo;
                float p10 = c[2] * w0 * em_hi, p11 = c[3] * w1 * em_hi;
                if (diag) {
                    const int jc = j0 + col0;
                    if (jc > r_lo) p00 = 0.f;
                    if (jc + 1 > r_lo) p01 = 0.f;
                    if (jc > r_hi) p10 = 0.f;
                    if (jc + 1 > r_hi) p11 = 0.f;
                }
                bsl += p00 + p01;
                bsh += p10 + p11;
                c[0] = p00; c[1] = p01; c[2] = p10; c[3] = p11;
            }

            // --- GEMM2: O += P V (P from registers, interleaved accumulators) ---
#pragma unroll
            for (int kt2 = 0; kt2 < 4; kt2++) {
                const float* s0 = accS[2 * kt2];
                const float* s1 = accS[2 * kt2 + 1];
                const float h00 = bf_hi(s0[0]), h01 = bf_hi(s0[1]);
                const float h02 = bf_hi(s0[2]), h03 = bf_hi(s0[3]);
                const float h10 = bf_hi(s1[0]), h11 = bf_hi(s1[1]);
                const float h12 = bf_hi(s1[2]), h13 = bf_hi(s1[3]);
                uint32_t ph[4], pl[4];
                ph[0] = pack_bf2(h00, h01);
                ph[1] = pack_bf2(h02, h03);
                ph[2] = pack_bf2(h10, h11);
                ph[3] = pack_bf2(h12, h13);
                pl[0] = pack_bf2(s0[0] - h00, s0[1] - h01);
                pl[1] = pack_bf2(s0[2] - h02, s0[3] - h03);
                pl[2] = pack_bf2(s1[0] - h10, s1[1] - h11);
                pl[3] = pack_bf2(s1[2] - h12, s1[3] - h13);
#pragma unroll
                for (int dpp = 0; dpp < 4; dpp++) {
                    const uint32_t v0a = sb + OFF_VHI + offV + kt2 * (16 * PITCH) + (2 * dpp) * 32;
                    const uint32_t v1a = v0a + 32;
                    uint32_t vh0[4], vl0[4], vh1[4], vl1[4];
                    ldsm4t(vh0, v0a);
                    ldsm4t(vh1, v1a);
                    ldsm4t(vl0, v0a + (OFF_VLO - OFF_VHI));
                    ldsm4t(vl1, v1a + (OFF_VLO - OFF_VHI));
                    float* o0 = accO[4 * dpp];
                    float* o1 = accO[4 * dpp + 1];
                    float* o2 = accO[4 * dpp + 2];
                    float* o3 = accO[4 * dpp + 3];
                    mma16816(o0, ph, vh0); mma16816(o2, ph, vh1);
                    mma16816(o1, ph, vh0 + 2); mma16816(o3, ph, vh1 + 2);
                    mma16816(o0, ph, vl0); mma16816(o2, ph, vl1);
                    mma16816(o1, ph, vl0 + 2); mma16816(o3, ph, vl1 + 2);
                    mma16816(o0, pl, vh0); mma16816(o2, pl, vh1);
                    mma16816(o1, pl, vh0 + 2); mma16816(o3, pl, vh1 + 2);
                }
            }
        }

        // --- reduce rowsums across quad, store partials ---
        bsl += __shfl_xor_sync(0xffffffffu, bsl, 1);
        bsl += __shfl_xor_sync(0xffffffffu, bsl, 2);
        bsh += __shfl_xor_sync(0xffffffffu, bsh, 1);
        bsh += __shfl_xor_sync(0xffffffffu, bsh, 2);
        if (qc == 0) {
            g_bpart[par][hb + r_lo] = bsl;
            g_bpart[par][hb + r_hi] = bsh;
        }
        float* od = g_Opart[par];
#pragma unroll
        for (int dt = 0; dt < 16; dt++) {
            const int col = h * HD + dt * 8 + 2 * qc;
            *reinterpret_cast<float2*>(od + (size_t)r_lo * DIM + col) =
                make_float2(accO[dt][0], accO[dt][1]);
            *reinterpret_cast<float2*>(od + (size_t)r_hi * DIM + col) =
                make_float2(accO[dt][2], accO[dt][3]);
        }
    }
}

// ---------------- merge + denominator + GroupNorm ----------------
__global__ void merge_gn(float* __restrict__ out, const float* __restrict__ gn_w,
                         const float* __restrict__ gn_b) {
    const int s = blockIdx.x;
    const int h = threadIdx.x >> 5;
    const int lane = threadIdx.x & 31;
    const size_t off = (size_t)s * DIM + h * HD + lane * 4;

    const float4 a = *reinterpret_cast<const float4*>(g_Opart[0] + off);
    const float4 b4 = *reinterpret_cast<const float4*>(g_Opart[1] + off);
    const float bs = g_bpart[0][h * SEQ + s] + g_bpart[1][h * SEQ + s];
    const float inv = 1.0f / (fmaxf(fabsf(bs), g_nfloor[h * SEQ + s]) + 1e-6f);

    float4 x;
    x.x = (a.x + b4.x) * inv;
    x.y = (a.y + b4.y) * inv;
    x.z = (a.z + b4.z) * inv;
    x.w = (a.w + b4.w) * inv;

    float sum = x.x + x.y + x.z + x.w;
#pragma unroll
    for (int o = 16; o; o >>= 1) sum += __shfl_xor_sync(0xffffffffu, sum, o);
    const float mean = sum * (1.0f / 128.0f);
    const float d0 = x.x - mean, d1 = x.y - mean, d2 = x.z - mean, d3 = x.w - mean;
    float sq = d0 * d0 + d1 * d1 + d2 * d2 + d3 * d3;
#pragma unroll
    for (int o = 16; o; o >>= 1) sq += __shfl_xor_sync(0xffffffffu, sq, o);
    const float istd = rsqrtf(sq * (1.0f / 128.0f) + 1e-5f);

    const float4 w = *reinterpret_cast<const float4*>(gn_w + h * HD + lane * 4);
    const float4 bb = *reinterpret_cast<const float4*>(gn_b + h * HD + lane * 4);
    float4 y;
    y.x = d0 * istd * w.x + bb.x;
    y.y = d1 * istd * w.y + bb.y;
    y.z = d2 * istd * w.z + bb.z;
    y.w = d3 * istd * w.w + bb.w;
    *reinterpret_cast<float4*>(out + off) = y;
}

// ---------------- launch ----------------
extern "C" void kernel_launch(void* const* d_in, const int* in_sizes, int n_in,
                              void* d_out, int out_size) {
    const float* q = (const float*)d_in[0];
    const float* k = (const float*)d_in[1];
    const float* v = (const float*)d_in[2];
    const float* Wi_w = (const float*)d_in[3];
    const float* Wi_b = (const float*)d_in[4];
    const float* Wf_w = (const float*)d_in[5];
    const float* Wf_b = (const float*)d_in[6];
    const float* gn_w = (const float*)d_in[7];
    const float* gn_b = (const float*)d_in[8];
    float* out = (float*)d_out;

    gates_kernel<<<SEQ, 256>>>(q, k, v, Wi_w, Wi_b, Wf_w, Wf_b);
    scan_kernel<<<NHEADS, 256>>>();

    cudaFuncSetAttribute(mlstm_mma, cudaFuncAttributeMaxDynamicSharedMemorySize, SMEM_TOTAL);
    dim3 grid(16, NHEADS);
    mlstm_mma<<<grid, 256, SMEM_TOTAL>>>(q, k, v);

    merge_gn<<<SEQ, 256>>>(out, gn_w, gn_b);
}

// round 7
// speedup vs baseline: 1.2027x; 1.1636x over previous
#include <cuda_runtime.h>
#include <cuda_fp16.h>
#include <cstdint>
#include <math.h>

#define SEQ 2048
#define DIM 1024
#define NHEADS 8
#define HD 128
#define LOG2E 1.4426950408889634f
#define INV_TAU 0.088388347648318447f

// ---------------- scratch (device globals; no allocation) ----------------
__device__ float g_itilde[NHEADS * SEQ];
__device__ float g_logsig[NHEADS * SEQ];
__device__ float g_a2[NHEADS * SEQ];      // a_j * log2(e)
__device__ float g_M2[NHEADS * SEQ];      // M_i * log2(e)
__device__ float g_nfloor[NHEADS * SEQ];  // exp(-(csum_i + M_i))
__device__ float g_Opart[2][SEQ * DIM];   // partial O per column-parity
__device__ float g_bpart[2][NHEADS * SEQ];

// ---------------- smem layout (bytes). Row pitch = 136 fp16 = 272 B ----------------
#define PITCH 272
#define OFF_QHI 0          /* 128 x 272 = 34816 (Q hi only) */
#define OFF_KHI 34816      /* 64 x 272 = 17408 each */
#define OFF_KLO 52224
#define OFF_VHI 69632
#define OFF_VLO 87040
#define OFF_EA 104448      /* 68 floats */
#define EAF (OFF_EA / 4)
#define SMEM_TOTAL (OFF_EA + 272)

// ---------------- helpers ----------------
__device__ __forceinline__ uint32_t smem_u32(const void* p) {
    uint32_t a;
    asm("{ .reg .u64 t; cvta.to.shared.u64 t, %1; cvt.u32.u64 %0, t; }" : "=r"(a) : "l"(p));
    return a;
}
__device__ __forceinline__ void ldsm4(uint32_t* r, uint32_t addr) {
    asm volatile("ldmatrix.sync.aligned.m8n8.x4.shared.b16 {%0,%1,%2,%3}, [%4];"
                 : "=r"(r[0]), "=r"(r[1]), "=r"(r[2]), "=r"(r[3]) : "r"(addr));
}
__device__ __forceinline__ void ldsm4t(uint32_t* r, uint32_t addr) {
    asm volatile("ldmatrix.sync.aligned.m8n8.x4.trans.shared.b16 {%0,%1,%2,%3}, [%4];"
                 : "=r"(r[0]), "=r"(r[1]), "=r"(r[2]), "=r"(r[3]) : "r"(addr));
}
__device__ __forceinline__ void mma16816(float* d, const uint32_t* a, const uint32_t* b) {
    asm volatile(
        "mma.sync.aligned.m16n8k16.row.col.f32.f16.f16.f32 "
        "{%0,%1,%2,%3}, {%4,%5,%6,%7}, {%8,%9}, {%0,%1,%2,%3};"
        : "+f"(d[0]), "+f"(d[1]), "+f"(d[2]), "+f"(d[3])
        : "r"(a[0]), "r"(a[1]), "r"(a[2]), "r"(a[3]), "r"(b[0]), "r"(b[1]));
}
__device__ __forceinline__ uint32_t pack_hf2(float a, float b) {
    __half2 t = __floats2half2_rn(a, b);
    return *reinterpret_cast<uint32_t*>(&t);
}
__device__ __forceinline__ float hf_hi(float f) {
    return __half2float(__float2half_rn(f));
}

// ---------------- kernel A: gate projections (verified) ----------------
__global__ void gates_kernel(const float* __restrict__ q, const float* __restrict__ k,
                             const float* __restrict__ v,
                             const float* __restrict__ Wi_w, const float* __restrict__ Wi_b,
                             const float* __restrict__ Wf_w, const float* __restrict__ Wf_b) {
    const int s = blockIdx.x;
    const int h = threadIdx.x >> 5;
    const int lane = threadIdx.x & 31;
    const float* wi = Wi_w + h * 3 * DIM;
    const float* wf = Wf_w + h * 3 * DIM;
    const float* qr = q + (size_t)s * DIM;
    const float* kr = k + (size_t)s * DIM;
    const float* vr = v + (size_t)s * DIM;

    float si = 0.f, sf = 0.f;
#pragma unroll
    for (int m = 0; m < 8; m++) {
        const int d = m * 128 + lane * 4;
        const float4 xq = *reinterpret_cast<const float4*>(qr + d);
        const float4 xk = *reinterpret_cast<const float4*>(kr + d);
        const float4 xv = *reinterpret_cast<const float4*>(vr + d);
        float4 w0 = *reinterpret_cast<const float4*>(wi + d);
        float4 w1 = *reinterpret_cast<const float4*>(wi + DIM + d);
        float4 w2 = *reinterpret_cast<const float4*>(wi + 2 * DIM + d);
        si += xq.x * w0.x + xq.y * w0.y + xq.z * w0.z + xq.w * w0.w;
        si += xk.x * w1.x + xk.y * w1.y + xk.z * w1.z + xk.w * w1.w;
        si += xv.x * w2.x + xv.y * w2.y + xv.z * w2.z + xv.w * w2.w;
        w0 = *reinterpret_cast<const float4*>(wf + d);
        w1 = *reinterpret_cast<const float4*>(wf + DIM + d);
        w2 = *reinterpret_cast<const float4*>(wf + 2 * DIM + d);
        sf += xq.x * w0.x + xq.y * w0.y + xq.z * w0.z + xq.w * w0.w;
        sf += xk.x * w1.x + xk.y * w1.y + xk.z * w1.z + xk.w * w1.w;
        sf += xv.x * w2.x + xv.y * w2.y + xv.z * w2.z + xv.w * w2.w;
    }
#pragma unroll
    for (int o = 16; o; o >>= 1) {
        si += __shfl_xor_sync(0xffffffffu, si, o);
        sf += __shfl_xor_sync(0xffffffffu, sf, o);
    }
    if (lane == 0) {
        g_itilde[h * SEQ + s] = si + Wi_b[h];
        const float ft = sf + Wf_b[h];
        g_logsig[h * SEQ + s] = fminf(ft, 0.f) - log1pf(__expf(-fabsf(ft)));
    }
}

// ---------------- kernel B: per-head scans (verified) ----------------
__global__ void scan_kernel() {
    const int h = blockIdx.x;
    const int t = threadIdx.x;
    __shared__ float sc[256];

    float cs[8];
    float run = 0.f;
#pragma unroll
    for (int m = 0; m < 8; m++) {
        run += g_logsig[h * SEQ + t * 8 + m];
        cs[m] = run;
    }
    sc[t] = run;
    __syncthreads();
#pragma unroll
    for (int off = 1; off < 256; off <<= 1) {
        const float vv = sc[t];
        const float uu = (t >= off) ? sc[t - off] : 0.f;
        __syncthreads();
        sc[t] = vv + uu;
        __syncthreads();
    }
    const float base = (t == 0) ? 0.f : sc[t - 1];

    float a[8], amax[8], csum[8];
    float runm = -3.402823466e38f;
#pragma unroll
    for (int m = 0; m < 8; m++) {
        csum[m] = base + cs[m];
        a[m] = g_itilde[h * SEQ + t * 8 + m] - csum[m];
        runm = fmaxf(runm, a[m]);
        amax[m] = runm;
    }
    __syncthreads();
    sc[t] = runm;
    __syncthreads();
#pragma unroll
    for (int off = 1; off < 256; off <<= 1) {
        const float vv = sc[t];
        const float uu = (t >= off) ? sc[t - off] : -3.402823466e38f;
        __syncthreads();
        sc[t] = fmaxf(vv, uu);
        __syncthreads();
    }
    const float mbase = (t == 0) ? -3.402823466e38f : sc[t - 1];

#pragma unroll
    for (int m = 0; m < 8; m++) {
        const int j = h * SEQ + t * 8 + m;
        const float Mv = fmaxf(mbase, amax[m]);
        g_a2[j] = a[m] * LOG2E;
        g_M2[j] = Mv * LOG2E;
        g_nfloor[j] = exp2f(-(csum[m] + Mv) * LOG2E);
    }
}

// ---------------- main kernel: fp16 HMMA flash mLSTM (2-pass split) ----------------
// grid (16, 8): blockIdx.x = pair p (>>1) + column parity (&1); blockIdx.y = head.
__global__ void __launch_bounds__(256, 1)
mlstm_mma(const float* __restrict__ q, const float* __restrict__ k,
          const float* __restrict__ v) {
    extern __shared__ char smraw[];
    const uint32_t sb = smem_u32(smraw);
    float* smf = reinterpret_cast<float*>(smraw);

    const int tid = threadIdx.x;
    const int lane = tid & 31;
    const int warp = tid >> 5;
    const int qc = lane & 3;
    const int h = blockIdx.y, hb = h * SEQ;
    const int p = blockIdx.x >> 1, par = blockIdx.x & 1;
    const int m0 = warp * 16;

    const uint32_t offA = (uint32_t)(m0 + (lane & 15)) * PITCH + ((lane >> 4) * 8) * 2;
    const uint32_t offB = (uint32_t)(((lane >> 4) & 1) * 8 + (lane & 7)) * PITCH +
                          (((lane >> 3) & 1) * 8) * 2;
    const uint32_t offV = (uint32_t)(lane & 15) * PITCH + ((lane >> 4) * 8) * 2;

    for (int hs = 0; hs < 2; hs++) {
        const int rtc = hs ? (15 - p) : p;
        const int i0 = rtc * 128;
        __syncthreads();  // previous half finished reading Q

        // --- stage Q hi only (scaled by 1/tau) ---
        for (int idx = tid; idx < 128 * 32; idx += 256) {
            const int r = idx >> 5, c4 = (idx & 31) * 4;
            float4 f = *reinterpret_cast<const float4*>(q + (size_t)(i0 + r) * DIM + h * HD + c4);
            f.x *= INV_TAU; f.y *= INV_TAU; f.z *= INV_TAU; f.w *= INV_TAU;
            char* bp = smraw + OFF_QHI + r * PITCH + c4 * 2;
            *reinterpret_cast<uint32_t*>(bp) = pack_hf2(f.x, f.y);
            *reinterpret_cast<uint32_t*>(bp + 4) = pack_hf2(f.z, f.w);
        }

        const int r_lo = i0 + m0 + (lane >> 2);
        const int r_hi = r_lo + 8;
        const float m2_lo = g_M2[hb + r_lo];
        const float m2_hi = g_M2[hb + r_hi];

        float accO[16][4];
#pragma unroll
        for (int a = 0; a < 16; a++)
#pragma unroll
            for (int b = 0; b < 4; b++) accO[a][b] = 0.f;
        float bsl = 0.f, bsh = 0.f;

        const int n_ct = 2 * rtc + 2;
        for (int ct = par; ct < n_ct; ct += 2) {
            const int j0 = ct * 64;
            __syncthreads();  // previous tile done reading K/V

            // --- stage K and V hi/lo (fp16 split) ---
            for (int idx = tid; idx < 64 * 32; idx += 256) {
                const int r = idx >> 5, c4 = (idx & 31) * 4;
                const float4 f = *reinterpret_cast<const float4*>(k + (size_t)(j0 + r) * DIM + h * HD + c4);
                const float hx = hf_hi(f.x), hy = hf_hi(f.y), hz = hf_hi(f.z), hw = hf_hi(f.w);
                char* bp = smraw + OFF_KHI + r * PITCH + c4 * 2;
                *reinterpret_cast<uint32_t*>(bp) = pack_hf2(hx, hy);
                *reinterpret_cast<uint32_t*>(bp + 4) = pack_hf2(hz, hw);
                char* lp = bp + (OFF_KLO - OFF_KHI);
                *reinterpret_cast<uint32_t*>(lp) = pack_hf2(f.x - hx, f.y - hy);
                *reinterpret_cast<uint32_t*>(lp + 4) = pack_hf2(f.z - hz, f.w - hw);

                const float4 g = *reinterpret_cast<const float4*>(v + (size_t)(j0 + r) * DIM + h * HD + c4);
                const float gx = hf_hi(g.x), gy = hf_hi(g.y), gz = hf_hi(g.z), gw = hf_hi(g.w);
                char* vp = smraw + OFF_VHI + r * PITCH + c4 * 2;
                *reinterpret_cast<uint32_t*>(vp) = pack_hf2(gx, gy);
                *reinterpret_cast<uint32_t*>(vp + 4) = pack_hf2(gz, gw);
                char* wp = vp + (OFF_VLO - OFF_VHI);
                *reinterpret_cast<uint32_t*>(wp) = pack_hf2(g.x - gx, g.y - gy);
                *reinterpret_cast<uint32_t*>(wp + 4) = pack_hf2(g.z - gz, g.w - gw);
            }
            if (tid < 64) smf[EAF + tid] = exp2f(g_a2[hb + j0 + tid] - g_M2[hb + j0 + 63]);
            if (tid == 64) smf[EAF + 64] = g_M2[hb + j0 + 63];
            __syncthreads();

            // fully-masked warp-tiles: last (odd) col-tile, rows < j0
            const bool fskip = (ct == 2 * rtc + 1) && (warp < 4);
            if (fskip) continue;

            // --- GEMM1: S = Qh (Kh + Kl)^T  (2-pass fp16, interleaved accumulators) ---
            float accS[8][4];
#pragma unroll
            for (int a = 0; a < 8; a++)
#pragma unroll
                for (int b = 0; b < 4; b++) accS[a][b] = 0.f;

#pragma unroll
            for (int kt = 0; kt < 8; kt++) {
                uint32_t ah[4];
                ldsm4(ah, sb + OFF_QHI + offA + kt * 32);
#pragma unroll
                for (int np2 = 0; np2 < 2; np2++) {
                    const uint32_t b0a = sb + OFF_KHI + offB + (2 * np2) * (16 * PITCH) + kt * 32;
                    const uint32_t b1a = b0a + 16 * PITCH;
                    uint32_t bh0[4], bl0[4], bh1[4], bl1[4];
                    ldsm4(bh0, b0a);
                    ldsm4(bh1, b1a);
                    ldsm4(bl0, b0a + (OFF_KLO - OFF_KHI));
                    ldsm4(bl1, b1a + (OFF_KLO - OFF_KHI));
                    float* a0 = accS[4 * np2];
                    float* a1 = accS[4 * np2 + 1];
                    float* a2 = accS[4 * np2 + 2];
                    float* a3 = accS[4 * np2 + 3];
                    mma16816(a0, ah, bh0); mma16816(a2, ah, bh1);
                    mma16816(a1, ah, bh0 + 2); mma16816(a3, ah, bh1 + 2);
                    mma16816(a0, ah, bl0); mma16816(a2, ah, bl1);
                    mma16816(a1, ah, bl0 + 2); mma16816(a3, ah, bl1 + 2);
                }
            }

            // --- decay weights + causal mask + rowsum ---
            const float ref2 = smf[EAF + 64];
            const float em_lo = exp2f(ref2 - m2_lo);
            const float em_hi = exp2f(ref2 - m2_hi);
            const bool diag = (ct >= 2 * rtc);
#pragma unroll
            for (int nt = 0; nt < 8; nt++) {
                const int col0 = nt * 8 + 2 * qc;
                const float w0 = smf[EAF + col0], w1 = smf[EAF + col0 + 1];
                float* c = accS[nt];
                float p00 = c[0] * w0 * em_lo, p01 = c[1] * w1 * em_lo;
                float p10 = c[2] * w0 * em_hi, p11 = c[3] * w1 * em_hi;
                if (diag) {
                    const int jc = j0 + col0;
                    if (jc > r_lo) p00 = 0.f;
                    if (jc + 1 > r_lo) p01 = 0.f;
                    if (jc > r_hi) p10 = 0.f;
                    if (jc + 1 > r_hi) p11 = 0.f;
                }
                bsl += p00 + p01;
                bsh += p10 + p11;
                c[0] = p00; c[1] = p01; c[2] = p10; c[3] = p11;
            }

            // --- GEMM2: O += Ph (Vh + Vl)  (2-pass fp16, interleaved accumulators) ---
#pragma unroll
            for (int kt2 = 0; kt2 < 4; kt2++) {
                const float* s0 = accS[2 * kt2];
                const float* s1 = accS[2 * kt2 + 1];
                uint32_t ph[4];
                ph[0] = pack_hf2(s0[0], s0[1]);
                ph[1] = pack_hf2(s0[2], s0[3]);
                ph[2] = pack_hf2(s1[0], s1[1]);
                ph[3] = pack_hf2(s1[2], s1[3]);
#pragma unroll
                for (int dpp = 0; dpp < 4; dpp++) {
                    const uint32_t v0a = sb + OFF_VHI + offV + kt2 * (16 * PITCH) + (2 * dpp) * 32;
                    const uint32_t v1a = v0a + 32;
                    uint32_t vh0[4], vl0[4], vh1[4], vl1[4];
                    ldsm4t(vh0, v0a);
                    ldsm4t(vh1, v1a);
                    ldsm4t(vl0, v0a + (OFF_VLO - OFF_VHI));
                    ldsm4t(vl1, v1a + (OFF_VLO - OFF_VHI));
                    float* o0 = accO[4 * dpp];
                    float* o1 = accO[4 * dpp + 1];
                    float* o2 = accO[4 * dpp + 2];
                    float* o3 = accO[4 * dpp + 3];
                    mma16816(o0, ph, vh0); mma16816(o2, ph, vh1);
                    mma16816(o1, ph, vh0 + 2); mma16816(o3, ph, vh1 + 2);
                    mma16816(o0, ph, vl0); mma16816(o2, ph, vl1);
                    mma16816(o1, ph, vl0 + 2); mma16816(o3, ph, vl1 + 2);
                }
            }
        }

        // --- reduce rowsums across quad, store partials ---
        bsl += __shfl_xor_sync(0xffffffffu, bsl, 1);
        bsl += __shfl_xor_sync(0xffffffffu, bsl, 2);
        bsh += __shfl_xor_sync(0xffffffffu, bsh, 1);
        bsh += __shfl_xor_sync(0xffffffffu, bsh, 2);
        if (qc == 0) {
            g_bpart[par][hb + r_lo] = bsl;
            g_bpart[par][hb + r_hi] = bsh;
        }
        float* od = g_Opart[par];
#pragma unroll
        for (int dt = 0; dt < 16; dt++) {
            const int col = h * HD + dt * 8 + 2 * qc;
            *reinterpret_cast<float2*>(od + (size_t)r_lo * DIM + col) =
                make_float2(accO[dt][0], accO[dt][1]);
            *reinterpret_cast<float2*>(od + (size_t)r_hi * DIM + col) =
                make_float2(accO[dt][2], accO[dt][3]);
        }
    }
}

// ---------------- merge + denominator + GroupNorm ----------------
__global__ void merge_gn(float* __restrict__ out, const float* __restrict__ gn_w,
                         const float* __restrict__ gn_b) {
    const int s = blockIdx.x;
    const int h = threadIdx.x >> 5;
    const int lane = threadIdx.x & 31;
    const size_t off = (size_t)s * DIM + h * HD + lane * 4;

    const float4 a = *reinterpret_cast<const float4*>(g_Opart[0] + off);
    const float4 b4 = *reinterpret_cast<const float4*>(g_Opart[1] + off);
    const float bs = g_bpart[0][h * SEQ + s] + g_bpart[1][h * SEQ + s];
    const float inv = 1.0f / (fmaxf(fabsf(bs), g_nfloor[h * SEQ + s]) + 1e-6f);

    float4 x;
    x.x = (a.x + b4.x) * inv;
    x.y = (a.y + b4.y) * inv;
    x.z = (a.z + b4.z) * inv;
    x.w = (a.w + b4.w) * inv;

    float sum = x.x + x.y + x.z + x.w;
#pragma unroll
    for (int o = 16; o; o >>= 1) sum += __shfl_xor_sync(0xffffffffu, sum, o);
    const float mean = sum * (1.0f / 128.0f);
    const float d0 = x.x - mean, d1 = x.y - mean, d2 = x.z - mean, d3 = x.w - mean;
    float sq = d0 * d0 + d1 * d1 + d2 * d2 + d3 * d3;
#pragma unroll
    for (int o = 16; o; o >>= 1) sq += __shfl_xor_sync(0xffffffffu, sq, o);
    const float istd = rsqrtf(sq * (1.0f / 128.0f) + 1e-5f);

    const float4 w = *reinterpret_cast<const float4*>(gn_w + h * HD + lane * 4);
    const float4 bb = *reinterpret_cast<const float4*>(gn_b + h * HD + lane * 4);
    float4 y;
    y.x = d0 * istd * w.x + bb.x;
    y.y = d1 * istd * w.y + bb.y;
    y.z = d2 * istd * w.z + bb.z;
    y.w = d3 * istd * w.w + bb.w;
    *reinterpret_cast<float4*>(out + off) = y;
}

// ---------------- launch ----------------
extern "C" void kernel_launch(void* const* d_in, const int* in_sizes, int n_in,
                              void* d_out, int out_size) {
    const float* q = (const float*)d_in[0];
    const float* k = (const float*)d_in[1];
    const float* v = (const float*)d_in[2];
    const float* Wi_w = (const float*)d_in[3];
    const float* Wi_b = (const float*)d_in[4];
    const float* Wf_w = (const float*)d_in[5];
    const float* Wf_b = (const float*)d_in[6];
    const float* gn_w = (const float*)d_in[7];
    const float* gn_b = (const float*)d_in[8];
    float* out = (float*)d_out;

    gates_kernel<<<SEQ, 256>>>(q, k, v, Wi_w, Wi_b, Wf_w, Wf_b);
    scan_kernel<<<NHEADS, 256>>>();

    cudaFuncSetAttribute(mlstm_mma, cudaFuncAttributeMaxDynamicSharedMemorySize, SMEM_TOTAL);
    dim3 grid(16, NHEADS);
    mlstm_mma<<<grid, 256, SMEM_TOTAL>>>(q, k, v);

    merge_gn<<<SEQ, 256>>>(out, gn_w, gn_b);
}

// round 8
// speedup vs baseline: 1.5117x; 1.2570x over previous
#include <cuda_runtime.h>
#include <cuda_fp16.h>
#include <cstdint>
#include <math.h>

#define SEQ 2048
#define DIM 1024
#define NHEADS 8
#define HD 128
#define LOG2E 1.4426950408889634f
#define INV_TAU 0.088388347648318447f

// ---------------- scratch (device globals; no allocation) ----------------
__device__ float g_itilde[NHEADS * SEQ];
__device__ float g_logsig[NHEADS * SEQ];
__device__ float g_a2[NHEADS * SEQ];      // a_j * log2(e)
__device__ float g_M2[NHEADS * SEQ];      // M_i * log2(e)
__device__ float g_nfloor[NHEADS * SEQ];  // exp(-(csum_i + M_i))
__device__ float g_Opart[2][SEQ * DIM];   // partial O per column-parity
__device__ float g_bpart[2][NHEADS * SEQ];

// ---------------- smem layout (bytes). Row pitch = 136 fp16 = 272 B ----------------
#define PITCH 272
#define OFF_QHI 0          /* 128 x 272 = 34816 */
#define OFF_KHI 34816      /* 64 x 272 = 17408 */
#define OFF_VHI 52224      /* 64 x 272 = 17408 */
#define OFF_EA 69632       /* 68 floats */
#define EAF (OFF_EA / 4)
#define SMEM_TOTAL (OFF_EA + 272)

// ---------------- helpers ----------------
__device__ __forceinline__ uint32_t smem_u32(const void* p) {
    uint32_t a;
    asm("{ .reg .u64 t; cvta.to.shared.u64 t, %1; cvt.u32.u64 %0, t; }" : "=r"(a) : "l"(p));
    return a;
}
__device__ __forceinline__ void ldsm4(uint32_t* r, uint32_t addr) {
    asm volatile("ldmatrix.sync.aligned.m8n8.x4.shared.b16 {%0,%1,%2,%3}, [%4];"
                 : "=r"(r[0]), "=r"(r[1]), "=r"(r[2]), "=r"(r[3]) : "r"(addr));
}
__device__ __forceinline__ void ldsm4t(uint32_t* r, uint32_t addr) {
    asm volatile("ldmatrix.sync.aligned.m8n8.x4.trans.shared.b16 {%0,%1,%2,%3}, [%4];"
                 : "=r"(r[0]), "=r"(r[1]), "=r"(r[2]), "=r"(r[3]) : "r"(addr));
}
__device__ __forceinline__ void mma16816(float* d, const uint32_t* a, const uint32_t* b) {
    asm volatile(
        "mma.sync.aligned.m16n8k16.row.col.f32.f16.f16.f32 "
        "{%0,%1,%2,%3}, {%4,%5,%6,%7}, {%8,%9}, {%0,%1,%2,%3};"
        : "+f"(d[0]), "+f"(d[1]), "+f"(d[2]), "+f"(d[3])
        : "r"(a[0]), "r"(a[1]), "r"(a[2]), "r"(a[3]), "r"(b[0]), "r"(b[1]));
}
__device__ __forceinline__ uint32_t pack_hf2(float a, float b) {
    __half2 t = __floats2half2_rn(a, b);
    return *reinterpret_cast<uint32_t*>(&t);
}

// ---------------- kernel A: gate projections (verified) ----------------
__global__ void gates_kernel(const float* __restrict__ q, const float* __restrict__ k,
                             const float* __restrict__ v,
                             const float* __restrict__ Wi_w, const float* __restrict__ Wi_b,
                             const float* __restrict__ Wf_w, const float* __restrict__ Wf_b) {
    const int s = blockIdx.x;
    const int h = threadIdx.x >> 5;
    const int lane = threadIdx.x & 31;
    const float* wi = Wi_w + h * 3 * DIM;
    const float* wf = Wf_w + h * 3 * DIM;
    const float* qr = q + (size_t)s * DIM;
    const float* kr = k + (size_t)s * DIM;
    const float* vr = v + (size_t)s * DIM;

    float si = 0.f, sf = 0.f;
#pragma unroll
    for (int m = 0; m < 8; m++) {
        const int d = m * 128 + lane * 4;
        const float4 xq = *reinterpret_cast<const float4*>(qr + d);
        const float4 xk = *reinterpret_cast<const float4*>(kr + d);
        const float4 xv = *reinterpret_cast<const float4*>(vr + d);
        float4 w0 = *reinterpret_cast<const float4*>(wi + d);
        float4 w1 = *reinterpret_cast<const float4*>(wi + DIM + d);
        float4 w2 = *reinterpret_cast<const float4*>(wi + 2 * DIM + d);
        si += xq.x * w0.x + xq.y * w0.y + xq.z * w0.z + xq.w * w0.w;
        si += xk.x * w1.x + xk.y * w1.y + xk.z * w1.z + xk.w * w1.w;
        si += xv.x * w2.x + xv.y * w2.y + xv.z * w2.z + xv.w * w2.w;
        w0 = *reinterpret_cast<const float4*>(wf + d);
        w1 = *reinterpret_cast<const float4*>(wf + DIM + d);
        w2 = *reinterpret_cast<const float4*>(wf + 2 * DIM + d);
        sf += xq.x * w0.x + xq.y * w0.y + xq.z * w0.z + xq.w * w0.w;
        sf += xk.x * w1.x + xk.y * w1.y + xk.z * w1.z + xk.w * w1.w;
        sf += xv.x * w2.x + xv.y * w2.y + xv.z * w2.z + xv.w * w2.w;
    }
#pragma unroll
    for (int o = 16; o; o >>= 1) {
        si += __shfl_xor_sync(0xffffffffu, si, o);
        sf += __shfl_xor_sync(0xffffffffu, sf, o);
    }
    if (lane == 0) {
        g_itilde[h * SEQ + s] = si + Wi_b[h];
        const float ft = sf + Wf_b[h];
        g_logsig[h * SEQ + s] = fminf(ft, 0.f) - log1pf(__expf(-fabsf(ft)));
    }
}

// ---------------- kernel B: per-head scans (verified) ----------------
__global__ void scan_kernel() {
    const int h = blockIdx.x;
    const int t = threadIdx.x;
    __shared__ float sc[256];

    float cs[8];
    float run = 0.f;
#pragma unroll
    for (int m = 0; m < 8; m++) {
        run += g_logsig[h * SEQ + t * 8 + m];
        cs[m] = run;
    }
    sc[t] = run;
    __syncthreads();
#pragma unroll
    for (int off = 1; off < 256; off <<= 1) {
        const float vv = sc[t];
        const float uu = (t >= off) ? sc[t - off] : 0.f;
        __syncthreads();
        sc[t] = vv + uu;
        __syncthreads();
    }
    const float base = (t == 0) ? 0.f : sc[t - 1];

    float a[8], amax[8], csum[8];
    float runm = -3.402823466e38f;
#pragma unroll
    for (int m = 0; m < 8; m++) {
        csum[m] = base + cs[m];
        a[m] = g_itilde[h * SEQ + t * 8 + m] - csum[m];
        runm = fmaxf(runm, a[m]);
        amax[m] = runm;
    }
    __syncthreads();
    sc[t] = runm;
    __syncthreads();
#pragma unroll
    for (int off = 1; off < 256; off <<= 1) {
        const float vv = sc[t];
        const float uu = (t >= off) ? sc[t - off] : -3.402823466e38f;
        __syncthreads();
        sc[t] = fmaxf(vv, uu);
        __syncthreads();
    }
    const float mbase = (t == 0) ? -3.402823466e38f : sc[t - 1];

#pragma unroll
    for (int m = 0; m < 8; m++) {
        const int j = h * SEQ + t * 8 + m;
        const float Mv = fmaxf(mbase, amax[m]);
        g_a2[j] = a[m] * LOG2E;
        g_M2[j] = Mv * LOG2E;
        g_nfloor[j] = exp2f(-(csum[m] + Mv) * LOG2E);
    }
}

// ---------------- main kernel: plain fp16 HMMA flash mLSTM ----------------
// grid (16, 8): blockIdx.x = pair p (>>1) + column parity (&1); blockIdx.y = head.
__global__ void __launch_bounds__(256, 1)
mlstm_mma(const float* __restrict__ q, const float* __restrict__ k,
          const float* __restrict__ v) {
    extern __shared__ char smraw[];
    const uint32_t sb = smem_u32(smraw);
    float* smf = reinterpret_cast<float*>(smraw);

    const int tid = threadIdx.x;
    const int lane = tid & 31;
    const int warp = tid >> 5;
    const int qc = lane & 3;
    const int h = blockIdx.y, hb = h * SEQ;
    const int p = blockIdx.x >> 1, par = blockIdx.x & 1;
    const int m0 = warp * 16;

    const uint32_t offA = (uint32_t)(m0 + (lane & 15)) * PITCH + ((lane >> 4) * 8) * 2;
    const uint32_t offB = (uint32_t)(((lane >> 4) & 1) * 8 + (lane & 7)) * PITCH +
                          (((lane >> 3) & 1) * 8) * 2;
    const uint32_t offV = (uint32_t)(lane & 15) * PITCH + ((lane >> 4) * 8) * 2;

    for (int hs = 0; hs < 2; hs++) {
        const int rtc = hs ? (15 - p) : p;
        const int i0 = rtc * 128;
        __syncthreads();  // previous half finished reading Q

        // --- stage Q (fp16, scaled by 1/tau) ---
        for (int idx = tid; idx < 128 * 32; idx += 256) {
            const int r = idx >> 5, c4 = (idx & 31) * 4;
            float4 f = *reinterpret_cast<const float4*>(q + (size_t)(i0 + r) * DIM + h * HD + c4);
            f.x *= INV_TAU; f.y *= INV_TAU; f.z *= INV_TAU; f.w *= INV_TAU;
            char* bp = smraw + OFF_QHI + r * PITCH + c4 * 2;
            *reinterpret_cast<uint32_t*>(bp) = pack_hf2(f.x, f.y);
            *reinterpret_cast<uint32_t*>(bp + 4) = pack_hf2(f.z, f.w);
        }

        const int r_lo = i0 + m0 + (lane >> 2);
        const int r_hi = r_lo + 8;
        const float m2_lo = g_M2[hb + r_lo];
        const float m2_hi = g_M2[hb + r_hi];

        float accO[16][4];
#pragma unroll
        for (int a = 0; a < 16; a++)
#pragma unroll
            for (int b = 0; b < 4; b++) accO[a][b] = 0.f;
        float bsl = 0.f, bsh = 0.f;

        const int n_ct = 2 * rtc + 2;
        for (int ct = par; ct < n_ct; ct += 2) {
            const int j0 = ct * 64;
            __syncthreads();  // previous tile done reading K/V

            // --- stage K and V (fp16) ---
            for (int idx = tid; idx < 64 * 32; idx += 256) {
                const int r = idx >> 5, c4 = (idx & 31) * 4;
                const float4 f = *reinterpret_cast<const float4*>(k + (size_t)(j0 + r) * DIM + h * HD + c4);
                char* bp = smraw + OFF_KHI + r * PITCH + c4 * 2;
                *reinterpret_cast<uint32_t*>(bp) = pack_hf2(f.x, f.y);
                *reinterpret_cast<uint32_t*>(bp + 4) = pack_hf2(f.z, f.w);

                const float4 g = *reinterpret_cast<const float4*>(v + (size_t)(j0 + r) * DIM + h * HD + c4);
                char* vp = smraw + OFF_VHI + r * PITCH + c4 * 2;
                *reinterpret_cast<uint32_t*>(vp) = pack_hf2(g.x, g.y);
                *reinterpret_cast<uint32_t*>(vp + 4) = pack_hf2(g.z, g.w);
            }
            if (tid < 64) smf[EAF + tid] = exp2f(g_a2[hb + j0 + tid] - g_M2[hb + j0 + 63]);
            if (tid == 64) smf[EAF + 64] = g_M2[hb + j0 + 63];
            __syncthreads();

            // fully-masked warp-tiles: last (odd) col-tile, rows < j0
            const bool fskip = (ct == 2 * rtc + 1) && (warp < 4);
            if (fskip) continue;

            // --- GEMM1: S = Q K^T (fp16, interleaved accumulators) ---
            float accS[8][4];
#pragma unroll
            for (int a = 0; a < 8; a++)
#pragma unroll
                for (int b = 0; b < 4; b++) accS[a][b] = 0.f;

#pragma unroll
            for (int kt = 0; kt < 8; kt++) {
                uint32_t ah[4];
                ldsm4(ah, sb + OFF_QHI + offA + kt * 32);
#pragma unroll
                for (int np2 = 0; np2 < 2; np2++) {
                    const uint32_t b0a = sb + OFF_KHI + offB + (2 * np2) * (16 * PITCH) + kt * 32;
                    const uint32_t b1a = b0a + 16 * PITCH;
                    uint32_t bh0[4], bh1[4];
                    ldsm4(bh0, b0a);
                    ldsm4(bh1, b1a);
                    float* a0 = accS[4 * np2];
                    float* a1 = accS[4 * np2 + 1];
                    float* a2 = accS[4 * np2 + 2];
                    float* a3 = accS[4 * np2 + 3];
                    mma16816(a0, ah, bh0); mma16816(a2, ah, bh1);
                    mma16816(a1, ah, bh0 + 2); mma16816(a3, ah, bh1 + 2);
                }
            }

            // --- decay weights + causal mask + rowsum ---
            const float ref2 = smf[EAF + 64];
            const float em_lo = exp2f(ref2 - m2_lo);
            const float em_hi = exp2f(ref2 - m2_hi);
            const bool diag = (ct >= 2 * rtc);
#pragma unroll
            for (int nt = 0; nt < 8; nt++) {
                const int col0 = nt * 8 + 2 * qc;
                const float w0 = smf[EAF + col0], w1 = smf[EAF + col0 + 1];
                float* c = accS[nt];
                float p00 = c[0] * w0 * em_lo, p01 = c[1] * w1 * em_lo;
                float p10 = c[2] * w0 * em_hi, p11 = c[3] * w1 * em_hi;
                if (diag) {
                    const int jc = j0 + col0;
                    if (jc > r_lo) p00 = 0.f;
                    if (jc + 1 > r_lo) p01 = 0.f;
                    if (jc > r_hi) p10 = 0.f;
                    if (jc + 1 > r_hi) p11 = 0.f;
                }
                bsl += p00 + p01;
                bsh += p10 + p11;
                c[0] = p00; c[1] = p01; c[2] = p10; c[3] = p11;
            }

            // --- GEMM2: O += P V (fp16, interleaved accumulators) ---
#pragma unroll
            for (int kt2 = 0; kt2 < 4; kt2++) {
                const float* s0 = accS[2 * kt2];
                const float* s1 = accS[2 * kt2 + 1];
                uint32_t ph[4];
                ph[0] = pack_hf2(s0[0], s0[1]);
                ph[1] = pack_hf2(s0[2], s0[3]);
                ph[2] = pack_hf2(s1[0], s1[1]);
                ph[3] = pack_hf2(s1[2], s1[3]);
#pragma unroll
                for (int dpp = 0; dpp < 4; dpp++) {
                    const uint32_t v0a = sb + OFF_VHI + offV + kt2 * (16 * PITCH) + (2 * dpp) * 32;
                    const uint32_t v1a = v0a + 32;
                    uint32_t vh0[4], vh1[4];
                    ldsm4t(vh0, v0a);
                    ldsm4t(vh1, v1a);
                    float* o0 = accO[4 * dpp];
                    float* o1 = accO[4 * dpp + 1];
                    float* o2 = accO[4 * dpp + 2];
                    float* o3 = accO[4 * dpp + 3];
                    mma16816(o0, ph, vh0); mma16816(o2, ph, vh1);
                    mma16816(o1, ph, vh0 + 2); mma16816(o3, ph, vh1 + 2);
                }
            }
        }

        // --- reduce rowsums across quad, store partials ---
        bsl += __shfl_xor_sync(0xffffffffu, bsl, 1);
        bsl += __shfl_xor_sync(0xffffffffu, bsl, 2);
        bsh += __shfl_xor_sync(0xffffffffu, bsh, 1);
        bsh += __shfl_xor_sync(0xffffffffu, bsh, 2);
        if (qc == 0) {
            g_bpart[par][hb + r_lo] = bsl;
            g_bpart[par][hb + r_hi] = bsh;
        }
        float* od = g_Opart[par];
#pragma unroll
        for (int dt = 0; dt < 16; dt++) {
            const int col = h * HD + dt * 8 + 2 * qc;
            *reinterpret_cast<float2*>(od + (size_t)r_lo * DIM + col) =
                make_float2(accO[dt][0], accO[dt][1]);
            *reinterpret_cast<float2*>(od + (size_t)r_hi * DIM + col) =
                make_float2(accO[dt][2], accO[dt][3]);
        }
    }
}

// ---------------- merge + denominator + GroupNorm ----------------
__global__ void merge_gn(float* __restrict__ out, const float* __restrict__ gn_w,
                         const float* __restrict__ gn_b) {
    const int s = blockIdx.x;
    const int h = threadIdx.x >> 5;
    const int lane = threadIdx.x & 31;
    const size_t off = (size_t)s * DIM + h * HD + lane * 4;

    const float4 a = *reinterpret_cast<const float4*>(g_Opart[0] + off);
    const float4 b4 = *reinterpret_cast<const float4*>(g_Opart[1] + off);
    const float bs = g_bpart[0][h * SEQ + s] + g_bpart[1][h * SEQ + s];
    const float inv = 1.0f / (fmaxf(fabsf(bs), g_nfloor[h * SEQ + s]) + 1e-6f);

    float4 x;
    x.x = (a.x + b4.x) * inv;
    x.y = (a.y + b4.y) * inv;
    x.z = (a.z + b4.z) * inv;
    x.w = (a.w + b4.w) * inv;

    float sum = x.x + x.y + x.z + x.w;
#pragma unroll
    for (int o = 16; o; o >>= 1) sum += __shfl_xor_sync(0xffffffffu, sum, o);
    const float mean = sum * (1.0f / 128.0f);
    const float d0 = x.x - mean, d1 = x.y - mean, d2 = x.z - mean, d3 = x.w - mean;
    float sq = d0 * d0 + d1 * d1 + d2 * d2 + d3 * d3;
#pragma unroll
    for (int o = 16; o; o >>= 1) sq += __shfl_xor_sync(0xffffffffu, sq, o);
    const float istd = rsqrtf(sq * (1.0f / 128.0f) + 1e-5f);

    const float4 w = *reinterpret_cast<const float4*>(gn_w + h * HD + lane * 4);
    const float4 bb = *reinterpret_cast<const float4*>(gn_b + h * HD + lane * 4);
    float4 y;
    y.x = d0 * istd * w.x + bb.x;
    y.y = d1 * istd * w.y + bb.y;
    y.z = d2 * istd * w.z + bb.z;
    y.w = d3 * istd * w.w + bb.w;
    *reinterpret_cast<float4*>(out + off) = y;
}

// ---------------- launch ----------------
extern "C" void kernel_launch(void* const* d_in, const int* in_sizes, int n_in,
                              void* d_out, int out_size) {
    const float* q = (const float*)d_in[0];
    const float* k = (const float*)d_in[1];
    const float* v = (const float*)d_in[2];
    const float* Wi_w = (const float*)d_in[3];
    const float* Wi_b = (const float*)d_in[4];
    const float* Wf_w = (const float*)d_in[5];
    const float* Wf_b = (const float*)d_in[6];
    const float* gn_w = (const float*)d_in[7];
    const float* gn_b = (const float*)d_in[8];
    float* out = (float*)d_out;

    gates_kernel<<<SEQ, 256>>>(q, k, v, Wi_w, Wi_b, Wf_w, Wf_b);
    scan_kernel<<<NHEADS, 256>>>();

    cudaFuncSetAttribute(mlstm_mma, cudaFuncAttributeMaxDynamicSharedMemorySize, SMEM_TOTAL);
    dim3 grid(16, NHEADS);
    mlstm_mma<<<grid, 256, SMEM_TOTAL>>>(q, k, v);

    merge_gn<<<SEQ, 256>>>(out, gn_w, gn_b);
}

// round 9
// speedup vs baseline: 1.7407x; 1.1515x over previous
#include <cuda_runtime.h>
#include <cuda_fp16.h>
#include <cstdint>
#include <math.h>

#define SEQ 2048
#define DIM 1024
#define NHEADS 8
#define HD 128
#define LOG2E 1.4426950408889634f
#define INV_TAU 0.088388347648318447f

// ---------------- scratch (device globals; no allocation) ----------------
__device__ float g_itilde[NHEADS * SEQ];
__device__ float g_logsig[NHEADS * SEQ];
__device__ float g_a2[NHEADS * SEQ];      // a_j * log2(e)
__device__ float g_M2[NHEADS * SEQ];      // M_i * log2(e)
__device__ float g_nfloor[NHEADS * SEQ];  // exp(-(csum_i + M_i))
__device__ float g_Opart[2][SEQ * DIM];   // partial O per column-parity
__device__ float g_bpart[2][NHEADS * SEQ];
__device__ __half g_q16[SEQ * DIM];       // fp16 copies (written by gates_kernel)
__device__ __half g_k16[SEQ * DIM];
__device__ __half g_v16[SEQ * DIM];

// ---------------- smem layout (bytes). Row pitch = 136 fp16 = 272 B ----------------
#define PITCH 272
#define OFF_Q 0            /* 128 x 272 = 34816 */
#define OFF_KV 34816       /* 2 buffers x (K 17408 + V 17408) */
#define KVB_STRIDE 34816
#define V_IN_BUF 17408
#define OFF_EA 104448      /* 2 x 68 floats */
#define EAF (OFF_EA / 4)
#define SMEM_TOTAL (OFF_EA + 2 * 272)

// ---------------- helpers ----------------
__device__ __forceinline__ uint32_t smem_u32(const void* p) {
    uint32_t a;
    asm("{ .reg .u64 t; cvta.to.shared.u64 t, %1; cvt.u32.u64 %0, t; }" : "=r"(a) : "l"(p));
    return a;
}
__device__ __forceinline__ void cp16(uint32_t dst, const void* src) {
    asm volatile("cp.async.cg.shared.global [%0], [%1], 16;" :: "r"(dst), "l"(src));
}
#define CP_COMMIT() asm volatile("cp.async.commit_group;" ::: "memory")
#define CP_WAIT(n) asm volatile("cp.async.wait_group %0;" :: "n"(n) : "memory")
__device__ __forceinline__ void ldsm4(uint32_t* r, uint32_t addr) {
    asm volatile("ldmatrix.sync.aligned.m8n8.x4.shared.b16 {%0,%1,%2,%3}, [%4];"
                 : "=r"(r[0]), "=r"(r[1]), "=r"(r[2]), "=r"(r[3]) : "r"(addr));
}
__device__ __forceinline__ void ldsm4t(uint32_t* r, uint32_t addr) {
    asm volatile("ldmatrix.sync.aligned.m8n8.x4.trans.shared.b16 {%0,%1,%2,%3}, [%4];"
                 : "=r"(r[0]), "=r"(r[1]), "=r"(r[2]), "=r"(r[3]) : "r"(addr));
}
__device__ __forceinline__ void mma16816(float* d, const uint32_t* a, const uint32_t* b) {
    asm volatile(
        "mma.sync.aligned.m16n8k16.row.col.f32.f16.f16.f32 "
        "{%0,%1,%2,%3}, {%4,%5,%6,%7}, {%8,%9}, {%0,%1,%2,%3};"
        : "+f"(d[0]), "+f"(d[1]), "+f"(d[2]), "+f"(d[3])
        : "r"(a[0]), "r"(a[1]), "r"(a[2]), "r"(a[3]), "r"(b[0]), "r"(b[1]));
}
__device__ __forceinline__ uint32_t pack_hf2(float a, float b) {
    __half2 t = __floats2half2_rn(a, b);
    return *reinterpret_cast<uint32_t*>(&t);
}

// ---------------- kernel A: gate projections + fp16 conversion ----------------
__global__ void gates_kernel(const float* __restrict__ q, const float* __restrict__ k,
                             const float* __restrict__ v,
                             const float* __restrict__ Wi_w, const float* __restrict__ Wi_b,
                             const float* __restrict__ Wf_w, const float* __restrict__ Wf_b) {
    const int s = blockIdx.x;
    const int h = threadIdx.x >> 5;
    const int lane = threadIdx.x & 31;
    const float* wi = Wi_w + h * 3 * DIM;
    const float* wf = Wf_w + h * 3 * DIM;
    const float* qr = q + (size_t)s * DIM;
    const float* kr = k + (size_t)s * DIM;
    const float* vr = v + (size_t)s * DIM;

    float si = 0.f, sf = 0.f;
#pragma unroll
    for (int m = 0; m < 8; m++) {
        const int d = m * 128 + lane * 4;
        const float4 xq = *reinterpret_cast<const float4*>(qr + d);
        const float4 xk = *reinterpret_cast<const float4*>(kr + d);
        const float4 xv = *reinterpret_cast<const float4*>(vr + d);

        // fp16 copies (warp 0 -> q16, warp 1 -> k16, warp 2 -> v16)
        if (h == 0) {
            *reinterpret_cast<uint2*>(g_q16 + (size_t)s * DIM + d) =
                make_uint2(pack_hf2(xq.x, xq.y), pack_hf2(xq.z, xq.w));
        } else if (h == 1) {
            *reinterpret_cast<uint2*>(g_k16 + (size_t)s * DIM + d) =
                make_uint2(pack_hf2(xk.x, xk.y), pack_hf2(xk.z, xk.w));
        } else if (h == 2) {
            *reinterpret_cast<uint2*>(g_v16 + (size_t)s * DIM + d) =
                make_uint2(pack_hf2(xv.x, xv.y), pack_hf2(xv.z, xv.w));
        }

        float4 w0 = *reinterpret_cast<const float4*>(wi + d);
        float4 w1 = *reinterpret_cast<const float4*>(wi + DIM + d);
        float4 w2 = *reinterpret_cast<const float4*>(wi + 2 * DIM + d);
        si += xq.x * w0.x + xq.y * w0.y + xq.z * w0.z + xq.w * w0.w;
        si += xk.x * w1.x + xk.y * w1.y + xk.z * w1.z + xk.w * w1.w;
        si += xv.x * w2.x + xv.y * w2.y + xv.z * w2.z + xv.w * w2.w;
        w0 = *reinterpret_cast<const float4*>(wf + d);
        w1 = *reinterpret_cast<const float4*>(wf + DIM + d);
        w2 = *reinterpret_cast<const float4*>(wf + 2 * DIM + d);
        sf += xq.x * w0.x + xq.y * w0.y + xq.z * w0.z + xq.w * w0.w;
        sf += xk.x * w1.x + xk.y * w1.y + xk.z * w1.z + xk.w * w1.w;
        sf += xv.x * w2.x + xv.y * w2.y + xv.z * w2.z + xv.w * w2.w;
    }
#pragma unroll
    for (int o = 16; o; o >>= 1) {
        si += __shfl_xor_sync(0xffffffffu, si, o);
        sf += __shfl_xor_sync(0xffffffffu, sf, o);
    }
    if (lane == 0) {
        g_itilde[h * SEQ + s] = si + Wi_b[h];
        const float ft = sf + Wf_b[h];
        g_logsig[h * SEQ + s] = fminf(ft, 0.f) - log1pf(__expf(-fabsf(ft)));
    }
}

// ---------------- kernel B: per-head scans (verified) ----------------
__global__ void scan_kernel() {
    const int h = blockIdx.x;
    const int t = threadIdx.x;
    __shared__ float sc[256];

    float cs[8];
    float run = 0.f;
#pragma unroll
    for (int m = 0; m < 8; m++) {
        run += g_logsig[h * SEQ + t * 8 + m];
        cs[m] = run;
    }
    sc[t] = run;
    __syncthreads();
#pragma unroll
    for (int off = 1; off < 256; off <<= 1) {
        const float vv = sc[t];
        const float uu = (t >= off) ? sc[t - off] : 0.f;
        __syncthreads();
        sc[t] = vv + uu;
        __syncthreads();
    }
    const float base = (t == 0) ? 0.f : sc[t - 1];

    float a[8], amax[8], csum[8];
    float runm = -3.402823466e38f;
#pragma unroll
    for (int m = 0; m < 8; m++) {
        csum[m] = base + cs[m];
        a[m] = g_itilde[h * SEQ + t * 8 + m] - csum[m];
        runm = fmaxf(runm, a[m]);
        amax[m] = runm;
    }
    __syncthreads();
    sc[t] = runm;
    __syncthreads();
#pragma unroll
    for (int off = 1; off < 256; off <<= 1) {
        const float vv = sc[t];
        const float uu = (t >= off) ? sc[t - off] : -3.402823466e38f;
        __syncthreads();
        sc[t] = fmaxf(vv, uu);
        __syncthreads();
    }
    const float mbase = (t == 0) ? -3.402823466e38f : sc[t - 1];

#pragma unroll
    for (int m = 0; m < 8; m++) {
        const int j = h * SEQ + t * 8 + m;
        const float Mv = fmaxf(mbase, amax[m]);
        g_a2[j] = a[m] * LOG2E;
        g_M2[j] = Mv * LOG2E;
        g_nfloor[j] = exp2f(-(csum[m] + Mv) * LOG2E);
    }
}

// issue one K/V column tile (64 rows) into stage buffer via cp.async
__device__ __forceinline__ void issue_kv(uint32_t sb, float* smf, int j0, int h, int hb,
                                         uint32_t kvb, int eaF, int tid) {
#pragma unroll
    for (int m = 0; m < 8; m++) {
        const int idx = tid + m * 256;          // 0..2047
        const int row = (idx >> 4) & 63;        // 64 rows per half
        const int chunk = idx & 15;             // 16 x 16B per row
        if (idx < 1024) {
            cp16(sb + kvb + row * PITCH + chunk * 16,
                 g_k16 + (size_t)(j0 + row) * DIM + h * HD + chunk * 8);
        } else {
            cp16(sb + kvb + V_IN_BUF + row * PITCH + chunk * 16,
                 g_v16 + (size_t)(j0 + row) * DIM + h * HD + chunk * 8);
        }
    }
    if (tid < 64) smf[eaF + tid] = exp2f(g_a2[hb + j0 + tid] - g_M2[hb + j0 + 63]);
    if (tid == 64) smf[eaF + 64] = g_M2[hb + j0 + 63];
}

// ---------------- main kernel: fp16 HMMA flash mLSTM, cp.async staged ----------------
// grid (16, 8): blockIdx.x = pair p (>>1) + column parity (&1); blockIdx.y = head.
__global__ void __launch_bounds__(256, 1)
mlstm_mma(float* __restrict__ dummy) {
    extern __shared__ char smraw[];
    const uint32_t sb = smem_u32(smraw);
    float* smf = reinterpret_cast<float*>(smraw);

    const int tid = threadIdx.x;
    const int lane = tid & 31;
    const int warp = tid >> 5;
    const int qc = lane & 3;
    const int h = blockIdx.y, hb = h * SEQ;
    const int p = blockIdx.x >> 1, par = blockIdx.x & 1;
    const int m0 = warp * 16;

    const uint32_t offA = (uint32_t)(m0 + (lane & 15)) * PITCH + ((lane >> 4) * 8) * 2;
    const uint32_t offB = (uint32_t)(((lane >> 4) & 1) * 8 + (lane & 7)) * PITCH +
                          (((lane >> 3) & 1) * 8) * 2;
    const uint32_t offV = (uint32_t)(lane & 15) * PITCH + ((lane >> 4) * 8) * 2;

    for (int hs = 0; hs < 2; hs++) {
        const int rtc = hs ? (15 - p) : p;
        const int i0 = rtc * 128;
        const int n_ct = 2 * rtc + 2;

        // --- prologue: issue Q + first K/V tile (one group) ---
#pragma unroll
        for (int m = 0; m < 8; m++) {
            const int idx = tid + m * 256;      // 0..2047
            const int row = idx >> 4;           // 128 rows
            const int chunk = idx & 15;
            cp16(sb + OFF_Q + row * PITCH + chunk * 16,
                 g_q16 + (size_t)(i0 + row) * DIM + h * HD + chunk * 8);
        }
        issue_kv(sb, smf, par * 64, h, hb, OFF_KV, EAF, tid);
        CP_COMMIT();

        const int r_lo = i0 + m0 + (lane >> 2);
        const int r_hi = r_lo + 8;
        const float m2_lo = g_M2[hb + r_lo];
        const float m2_hi = g_M2[hb + r_hi];

        float accO[16][4];
#pragma unroll
        for (int a = 0; a < 16; a++)
#pragma unroll
            for (int b = 0; b < 4; b++) accO[a][b] = 0.f;
        float bsl = 0.f, bsh = 0.f;

        for (int ct = par, it = 0; ct < n_ct; ct += 2, it++) {
            const int j0 = ct * 64;
            const uint32_t kvb = OFF_KV + (uint32_t)(it & 1) * KVB_STRIDE;
            const int eaF = EAF + (it & 1) * 68;

            // issue next tile into the other buffer, then wait for current
            if (ct + 2 < n_ct) {
                issue_kv(sb, smf, (ct + 2) * 64, h, hb,
                         OFF_KV + (uint32_t)((it + 1) & 1) * KVB_STRIDE,
                         EAF + ((it + 1) & 1) * 68, tid);
                CP_COMMIT();
                CP_WAIT(1);
            } else {
                CP_WAIT(0);
            }
            __syncthreads();  // current tile (and Q on it==0) visible to all

            // fully-masked warp-tiles: last (odd) col-tile, rows < j0
            const bool fskip = (ct == 2 * rtc + 1) && (warp < 4);
            if (!fskip) {
                // --- GEMM1: S = Q K^T (fp16, interleaved accumulators) ---
                float accS[8][4];
#pragma unroll
                for (int a = 0; a < 8; a++)
#pragma unroll
                    for (int b = 0; b < 4; b++) accS[a][b] = 0.f;

#pragma unroll
                for (int kt = 0; kt < 8; kt++) {
                    uint32_t ah[4];
                    ldsm4(ah, sb + OFF_Q + offA + kt * 32);
#pragma unroll
                    for (int np2 = 0; np2 < 2; np2++) {
                        const uint32_t b0a = sb + kvb + offB + (2 * np2) * (16 * PITCH) + kt * 32;
                        const uint32_t b1a = b0a + 16 * PITCH;
                        uint32_t bh0[4], bh1[4];
                        ldsm4(bh0, b0a);
                        ldsm4(bh1, b1a);
                        float* a0 = accS[4 * np2];
                        float* a1 = accS[4 * np2 + 1];
                        float* a2 = accS[4 * np2 + 2];
                        float* a3 = accS[4 * np2 + 3];
                        mma16816(a0, ah, bh0); mma16816(a2, ah, bh1);
                        mma16816(a1, ah, bh0 + 2); mma16816(a3, ah, bh1 + 2);
                    }
                }

                // --- decay weights (incl. 1/tau) + causal mask + rowsum ---
                const float ref2 = smf[eaF + 64];
                const float em_lo = exp2f(ref2 - m2_lo) * INV_TAU;
                const float em_hi = exp2f(ref2 - m2_hi) * INV_TAU;
                const bool diag = (ct >= 2 * rtc);
#pragma unroll
                for (int nt = 0; nt < 8; nt++) {
                    const int col0 = nt * 8 + 2 * qc;
                    const float w0 = smf[eaF + col0], w1 = smf[eaF + col0 + 1];
                    float* c = accS[nt];
                    float p00 = c[0] * w0 * em_lo, p01 = c[1] * w1 * em_lo;
                    float p10 = c[2] * w0 * em_hi, p11 = c[3] * w1 * em_hi;
                    if (diag) {
                        const int jc = j0 + col0;
                        if (jc > r_lo) p00 = 0.f;
                        if (jc + 1 > r_lo) p01 = 0.f;
                        if (jc > r_hi) p10 = 0.f;
                        if (jc + 1 > r_hi) p11 = 0.f;
                    }
                    bsl += p00 + p01;
                    bsh += p10 + p11;
                    c[0] = p00; c[1] = p01; c[2] = p10; c[3] = p11;
                }

                // --- GEMM2: O += P V (fp16, interleaved accumulators) ---
#pragma unroll
                for (int kt2 = 0; kt2 < 4; kt2++) {
                    const float* s0 = accS[2 * kt2];
                    const float* s1 = accS[2 * kt2 + 1];
                    uint32_t ph[4];
                    ph[0] = pack_hf2(s0[0], s0[1]);
                    ph[1] = pack_hf2(s0[2], s0[3]);
                    ph[2] = pack_hf2(s1[0], s1[1]);
                    ph[3] = pack_hf2(s1[2], s1[3]);
#pragma unroll
                    for (int dpp = 0; dpp < 4; dpp++) {
                        const uint32_t v0a = sb + kvb + V_IN_BUF + offV + kt2 * (16 * PITCH) + (2 * dpp) * 32;
                        const uint32_t v1a = v0a + 32;
                        uint32_t vh0[4], vh1[4];
                        ldsm4t(vh0, v0a);
                        ldsm4t(vh1, v1a);
                        float* o0 = accO[4 * dpp];
                        float* o1 = accO[4 * dpp + 1];
                        float* o2 = accO[4 * dpp + 2];
                        float* o3 = accO[4 * dpp + 3];
                        mma16816(o0, ph, vh0); mma16816(o2, ph, vh1);
                        mma16816(o1, ph, vh0 + 2); mma16816(o3, ph, vh1 + 2);
                    }
                }
            }
            __syncthreads();  // all reads of current buffer done before it is reused
        }

        // --- reduce rowsums across quad, store partials ---
        bsl += __shfl_xor_sync(0xffffffffu, bsl, 1);
        bsl += __shfl_xor_sync(0xffffffffu, bsl, 2);
        bsh += __shfl_xor_sync(0xffffffffu, bsh, 1);
        bsh += __shfl_xor_sync(0xffffffffu, bsh, 2);
        if (qc == 0) {
            g_bpart[par][hb + r_lo] = bsl;
            g_bpart[par][hb + r_hi] = bsh;
        }
        float* od = g_Opart[par];
#pragma unroll
        for (int dt = 0; dt < 16; dt++) {
            const int col = h * HD + dt * 8 + 2 * qc;
            *reinterpret_cast<float2*>(od + (size_t)r_lo * DIM + col) =
                make_float2(accO[dt][0], accO[dt][1]);
            *reinterpret_cast<float2*>(od + (size_t)r_hi * DIM + col) =
                make_float2(accO[dt][2], accO[dt][3]);
        }
    }
}

// ---------------- merge + denominator + GroupNorm ----------------
__global__ void merge_gn(float* __restrict__ out, const float* __restrict__ gn_w,
                         const float* __restrict__ gn_b) {
    const int s = blockIdx.x;
    const int h = threadIdx.x >> 5;
    const int lane = threadIdx.x & 31;
    const size_t off = (size_t)s * DIM + h * HD + lane * 4;

    const float4 a = *reinterpret_cast<const float4*>(g_Opart[0] + off);
    const float4 b4 = *reinterpret_cast<const float4*>(g_Opart[1] + off);
    const float bs = g_bpart[0][h * SEQ + s] + g_bpart[1][h * SEQ + s];
    const float inv = 1.0f / (fmaxf(fabsf(bs), g_nfloor[h * SEQ + s]) + 1e-6f);

    float4 x;
    x.x = (a.x + b4.x) * inv;
    x.y = (a.y + b4.y) * inv;
    x.z = (a.z + b4.z) * inv;
    x.w = (a.w + b4.w) * inv;

    float sum = x.x + x.y + x.z + x.w;
#pragma unroll
    for (int o = 16; o; o >>= 1) sum += __shfl_xor_sync(0xffffffffu, sum, o);
    const float mean = sum * (1.0f / 128.0f);
    const float d0 = x.x - mean, d1 = x.y - mean, d2 = x.z - mean, d3 = x.w - mean;
    float sq = d0 * d0 + d1 * d1 + d2 * d2 + d3 * d3;
#pragma unroll
    for (int o = 16; o; o >>= 1) sq += __shfl_xor_sync(0xffffffffu, sq, o);
    const float istd = rsqrtf(sq * (1.0f / 128.0f) + 1e-5f);

    const float4 w = *reinterpret_cast<const float4*>(gn_w + h * HD + lane * 4);
    const float4 bb = *reinterpret_cast<const float4*>(gn_b + h * HD + lane * 4);
    float4 y;
    y.x = d0 * istd * w.x + bb.x;
    y.y = d1 * istd * w.y + bb.y;
    y.z = d2 * istd * w.z + bb.z;
    y.w = d3 * istd * w.w + bb.w;
    *reinterpret_cast<float4*>(out + off) = y;
}

// ---------------- launch ----------------
extern "C" void kernel_launch(void* const* d_in, const int* in_sizes, int n_in,
                              void* d_out, int out_size) {
    const float* q = (const float*)d_in[0];
    const float* k = (const float*)d_in[1];
    const float* v = (const float*)d_in[2];
    const float* Wi_w = (const float*)d_in[3];
    const float* Wi_b = (const float*)d_in[4];
    const float* Wf_w = (const float*)d_in[5];
    const float* Wf_b = (const float*)d_in[6];
    const float* gn_w = (const float*)d_in[7];
    const float* gn_b = (const float*)d_in[8];
    float* out = (float*)d_out;

    gates_kernel<<<SEQ, 256>>>(q, k, v, Wi_w, Wi_b, Wf_w, Wf_b);
    scan_kernel<<<NHEADS, 256>>>();

    cudaFuncSetAttribute(mlstm_mma, cudaFuncAttributeMaxDynamicSharedMemorySize, SMEM_TOTAL);
    dim3 grid(16, NHEADS);
    mlstm_mma<<<grid, 256, SMEM_TOTAL>>>(out);

    merge_gn<<<SEQ, 256>>>(out, gn_w, gn_b);
}

// round 10
// speedup vs baseline: 1.7642x; 1.0135x over previous
#include <cuda_runtime.h>
#include <cuda_fp16.h>
#include <cstdint>
#include <math.h>

#define SEQ 2048
#define DIM 1024
#define NHEADS 8
#define HD 128
#define LOG2E 1.4426950408889634f
#define INV_TAU 0.088388347648318447f

// ---------------- scratch (device globals; no allocation) ----------------
__device__ float g_itilde[NHEADS * SEQ];
__device__ float g_logsig[NHEADS * SEQ];
__device__ float g_a2[NHEADS * SEQ];      // a_j * log2(e)
__device__ float g_M2[NHEADS * SEQ];      // M_i * log2(e)
__device__ float g_nfloor[NHEADS * SEQ];  // exp(-(csum_i + M_i))
__device__ __half g_o16[2][SEQ * DIM];    // fp16 partial O per column-parity
__device__ float g_bpart[2][NHEADS * SEQ];
__device__ __half g_q16[SEQ * DIM];       // fp16 copies (written by gates_kernel)
__device__ __half g_k16[SEQ * DIM];
__device__ __half g_v16[SEQ * DIM];

// ---------------- smem layout (bytes). Row pitch = 136 fp16 = 272 B ----------------
#define PITCH 272
#define OFF_Q 0            /* 128 x 272 = 34816 */
#define OFF_KV 34816       /* 2 buffers x (K 17408 + V 17408) */
#define KVB_STRIDE 34816
#define V_IN_BUF 17408
#define OFF_EA 104448      /* 2 x 68 floats */
#define EAF (OFF_EA / 4)
#define SMEM_TOTAL (OFF_EA + 2 * 272)

// ---------------- helpers ----------------
__device__ __forceinline__ uint32_t smem_u32(const void* p) {
    uint32_t a;
    asm("{ .reg .u64 t; cvta.to.shared.u64 t, %1; cvt.u32.u64 %0, t; }" : "=r"(a) : "l"(p));
    return a;
}
__device__ __forceinline__ void cp16(uint32_t dst, const void* src) {
    asm volatile("cp.async.cg.shared.global [%0], [%1], 16;" :: "r"(dst), "l"(src));
}
#define CP_COMMIT() asm volatile("cp.async.commit_group;" ::: "memory")
#define CP_WAIT(n) asm volatile("cp.async.wait_group %0;" :: "n"(n) : "memory")
__device__ __forceinline__ void ldsm4(uint32_t* r, uint32_t addr) {
    asm volatile("ldmatrix.sync.aligned.m8n8.x4.shared.b16 {%0,%1,%2,%3}, [%4];"
                 : "=r"(r[0]), "=r"(r[1]), "=r"(r[2]), "=r"(r[3]) : "r"(addr));
}
__device__ __forceinline__ void ldsm4t(uint32_t* r, uint32_t addr) {
    asm volatile("ldmatrix.sync.aligned.m8n8.x4.trans.shared.b16 {%0,%1,%2,%3}, [%4];"
                 : "=r"(r[0]), "=r"(r[1]), "=r"(r[2]), "=r"(r[3]) : "r"(addr));
}
__device__ __forceinline__ void mma16816(float* d, const uint32_t* a, const uint32_t* b) {
    asm volatile(
        "mma.sync.aligned.m16n8k16.row.col.f32.f16.f16.f32 "
        "{%0,%1,%2,%3}, {%4,%5,%6,%7}, {%8,%9}, {%0,%1,%2,%3};"
        : "+f"(d[0]), "+f"(d[1]), "+f"(d[2]), "+f"(d[3])
        : "r"(a[0]), "r"(a[1]), "r"(a[2]), "r"(a[3]), "r"(b[0]), "r"(b[1]));
}
__device__ __forceinline__ uint32_t pack_hf2(float a, float b) {
    __half2 t = __floats2half2_rn(a, b);
    return *reinterpret_cast<uint32_t*>(&t);
}

// ---------------- kernel A: gate projections + fp16 conversion ----------------
__global__ void gates_kernel(const float* __restrict__ q, const float* __restrict__ k,
                             const float* __restrict__ v,
                             const float* __restrict__ Wi_w, const float* __restrict__ Wi_b,
                             const float* __restrict__ Wf_w, const float* __restrict__ Wf_b) {
    const int s = blockIdx.x;
    const int h = threadIdx.x >> 5;
    const int lane = threadIdx.x & 31;
    const float* wi = Wi_w + h * 3 * DIM;
    const float* wf = Wf_w + h * 3 * DIM;
    const float* qr = q + (size_t)s * DIM;
    const float* kr = k + (size_t)s * DIM;
    const float* vr = v + (size_t)s * DIM;

    float si = 0.f, sf = 0.f;
#pragma unroll
    for (int m = 0; m < 8; m++) {
        const int d = m * 128 + lane * 4;
        const float4 xq = *reinterpret_cast<const float4*>(qr + d);
        const float4 xk = *reinterpret_cast<const float4*>(kr + d);
        const float4 xv = *reinterpret_cast<const float4*>(vr + d);

        if (h == 0) {
            *reinterpret_cast<uint2*>(g_q16 + (size_t)s * DIM + d) =
                make_uint2(pack_hf2(xq.x, xq.y), pack_hf2(xq.z, xq.w));
        } else if (h == 1) {
            *reinterpret_cast<uint2*>(g_k16 + (size_t)s * DIM + d) =
                make_uint2(pack_hf2(xk.x, xk.y), pack_hf2(xk.z, xk.w));
        } else if (h == 2) {
            *reinterpret_cast<uint2*>(g_v16 + (size_t)s * DIM + d) =
                make_uint2(pack_hf2(xv.x, xv.y), pack_hf2(xv.z, xv.w));
        }

        float4 w0 = *reinterpret_cast<const float4*>(wi + d);
        float4 w1 = *reinterpret_cast<const float4*>(wi + DIM + d);
        float4 w2 = *reinterpret_cast<const float4*>(wi + 2 * DIM + d);
        si += xq.x * w0.x + xq.y * w0.y + xq.z * w0.z + xq.w * w0.w;
        si += xk.x * w1.x + xk.y * w1.y + xk.z * w1.z + xk.w * w1.w;
        si += xv.x * w2.x + xv.y * w2.y + xv.z * w2.z + xv.w * w2.w;
        w0 = *reinterpret_cast<const float4*>(wf + d);
        w1 = *reinterpret_cast<const float4*>(wf + DIM + d);
        w2 = *reinterpret_cast<const float4*>(wf + 2 * DIM + d);
        sf += xq.x * w0.x + xq.y * w0.y + xq.z * w0.z + xq.w * w0.w;
        sf += xk.x * w1.x + xk.y * w1.y + xk.z * w1.z + xk.w * w1.w;
        sf += xv.x * w2.x + xv.y * w2.y + xv.z * w2.z + xv.w * w2.w;
    }
#pragma unroll
    for (int o = 16; o; o >>= 1) {
        si += __shfl_xor_sync(0xffffffffu, si, o);
        sf += __shfl_xor_sync(0xffffffffu, sf, o);
    }
    if (lane == 0) {
        g_itilde[h * SEQ + s] = si + Wi_b[h];
        const float ft = sf + Wf_b[h];
        g_logsig[h * SEQ + s] = fminf(ft, 0.f) - log1pf(__expf(-fabsf(ft)));
    }
}

// ---------------- kernel B: per-head scans (verified) ----------------
__global__ void scan_kernel() {
    const int h = blockIdx.x;
    const int t = threadIdx.x;
    __shared__ float sc[256];

    float cs[8];
    float run = 0.f;
#pragma unroll
    for (int m = 0; m < 8; m++) {
        run += g_logsig[h * SEQ + t * 8 + m];
        cs[m] = run;
    }
    sc[t] = run;
    __syncthreads();
#pragma unroll
    for (int off = 1; off < 256; off <<= 1) {
        const float vv = sc[t];
        const float uu = (t >= off) ? sc[t - off] : 0.f;
        __syncthreads();
        sc[t] = vv + uu;
        __syncthreads();
    }
    const float base = (t == 0) ? 0.f : sc[t - 1];

    float a[8], amax[8], csum[8];
    float runm = -3.402823466e38f;
#pragma unroll
    for (int m = 0; m < 8; m++) {
        csum[m] = base + cs[m];
        a[m] = g_itilde[h * SEQ + t * 8 + m] - csum[m];
        runm = fmaxf(runm, a[m]);
        amax[m] = runm;
    }
    __syncthreads();
    sc[t] = runm;
    __syncthreads();
#pragma unroll
    for (int off = 1; off < 256; off <<= 1) {
        const float vv = sc[t];
        const float uu = (t >= off) ? sc[t - off] : -3.402823466e38f;
        __syncthreads();
        sc[t] = fmaxf(vv, uu);
        __syncthreads();
    }
    const float mbase = (t == 0) ? -3.402823466e38f : sc[t - 1];

#pragma unroll
    for (int m = 0; m < 8; m++) {
        const int j = h * SEQ + t * 8 + m;
        const float Mv = fmaxf(mbase, amax[m]);
        g_a2[j] = a[m] * LOG2E;
        g_M2[j] = Mv * LOG2E;
        g_nfloor[j] = exp2f(-(csum[m] + Mv) * LOG2E);
    }
}

// issue one K/V column tile (64 rows) into stage buffer via cp.async
__device__ __forceinline__ void issue_kv(uint32_t sb, float* smf, int j0, int h, int hb,
                                         uint32_t kvb, int eaF, int tid) {
#pragma unroll
    for (int m = 0; m < 8; m++) {
        const int idx = tid + m * 256;          // 0..2047
        const int row = (idx >> 4) & 63;        // 64 rows per half
        const int chunk = idx & 15;             // 16 x 16B per row
        if (idx < 1024) {
            cp16(sb + kvb + row * PITCH + chunk * 16,
                 g_k16 + (size_t)(j0 + row) * DIM + h * HD + chunk * 8);
        } else {
            cp16(sb + kvb + V_IN_BUF + row * PITCH + chunk * 16,
                 g_v16 + (size_t)(j0 + row) * DIM + h * HD + chunk * 8);
        }
    }
    if (tid < 64) smf[eaF + tid] = exp2f(g_a2[hb + j0 + tid] - g_M2[hb + j0 + 63]);
    if (tid == 64) smf[eaF + 64] = g_M2[hb + j0 + 63];
}

// ---------------- main kernel: fp16 HMMA flash mLSTM, Q in registers ----------------
// grid (16, 8): blockIdx.x = pair p (>>1) + column parity (&1); blockIdx.y = head.
__global__ void __launch_bounds__(256, 1)
mlstm_mma() {
    extern __shared__ char smraw[];
    const uint32_t sb = smem_u32(smraw);
    float* smf = reinterpret_cast<float*>(smraw);

    const int tid = threadIdx.x;
    const int lane = tid & 31;
    const int warp = tid >> 5;
    const int qc = lane & 3;
    const int h = blockIdx.y, hb = h * SEQ;
    const int p = blockIdx.x >> 1, par = blockIdx.x & 1;
    const int m0 = warp * 16;

    const uint32_t offA = (uint32_t)(m0 + (lane & 15)) * PITCH + ((lane >> 4) * 8) * 2;
    const uint32_t offB = (uint32_t)(((lane >> 4) & 1) * 8 + (lane & 7)) * PITCH +
                          (((lane >> 3) & 1) * 8) * 2;
    const uint32_t offV = (uint32_t)(lane & 15) * PITCH + ((lane >> 4) * 8) * 2;

    for (int hs = 0; hs < 2; hs++) {
        const int rtc = hs ? (15 - p) : p;
        const int i0 = rtc * 128;
        const int n_ct = 2 * rtc + 2;

        // --- prologue: issue Q + first K/V tile (one group) ---
#pragma unroll
        for (int m = 0; m < 8; m++) {
            const int idx = tid + m * 256;      // 0..2047
            const int row = idx >> 4;           // 128 rows
            const int chunk = idx & 15;
            cp16(sb + OFF_Q + row * PITCH + chunk * 16,
                 g_q16 + (size_t)(i0 + row) * DIM + h * HD + chunk * 8);
        }
        issue_kv(sb, smf, par * 64, h, hb, OFF_KV, EAF, tid);
        CP_COMMIT();

        const int r_lo = i0 + m0 + (lane >> 2);
        const int r_hi = r_lo + 8;
        const float m2_lo = g_M2[hb + r_lo];
        const float m2_hi = g_M2[hb + r_hi];

        float accO[16][4];
#pragma unroll
        for (int a = 0; a < 16; a++)
#pragma unroll
            for (int b = 0; b < 4; b++) accO[a][b] = 0.f;
        float bsl = 0.f, bsh = 0.f;

        uint32_t qfrag[8][4];   // Q fragments, loaded once per half
        bool qloaded = false;

        for (int ct = par, it = 0; ct < n_ct; ct += 2, it++) {
            const int j0 = ct * 64;
            const uint32_t kvb = OFF_KV + (uint32_t)(it & 1) * KVB_STRIDE;
            const int eaF = EAF + (it & 1) * 68;

            // issue next tile into the other buffer, then wait for current
            if (ct + 2 < n_ct) {
                issue_kv(sb, smf, (ct + 2) * 64, h, hb,
                         OFF_KV + (uint32_t)((it + 1) & 1) * KVB_STRIDE,
                         EAF + ((it + 1) & 1) * 68, tid);
                CP_COMMIT();
                CP_WAIT(1);
            } else {
                CP_WAIT(0);
            }
            __syncthreads();  // current tile (and Q on it==0) visible to all

            if (!qloaded) {
                qloaded = true;
#pragma unroll
                for (int kt = 0; kt < 8; kt++) ldsm4(qfrag[kt], sb + OFF_Q + offA + kt * 32);
            }

            // fully-masked warp-tiles: last (odd) col-tile, rows < j0
            const bool fskip = (ct == 2 * rtc + 1) && (warp < 4);
            if (!fskip) {
                // --- GEMM1: S = Q K^T (fp16, Q from registers) ---
                float accS[8][4];
#pragma unroll
                for (int a = 0; a < 8; a++)
#pragma unroll
                    for (int b = 0; b < 4; b++) accS[a][b] = 0.f;

#pragma unroll
                for (int kt = 0; kt < 8; kt++) {
#pragma unroll
                    for (int np2 = 0; np2 < 2; np2++) {
                        const uint32_t b0a = sb + kvb + offB + (2 * np2) * (16 * PITCH) + kt * 32;
                        const uint32_t b1a = b0a + 16 * PITCH;
                        uint32_t bh0[4], bh1[4];
                        ldsm4(bh0, b0a);
                        ldsm4(bh1, b1a);
                        float* a0 = accS[4 * np2];
                        float* a1 = accS[4 * np2 + 1];
                        float* a2 = accS[4 * np2 + 2];
                        float* a3 = accS[4 * np2 + 3];
                        mma16816(a0, qfrag[kt], bh0); mma16816(a2, qfrag[kt], bh1);
                        mma16816(a1, qfrag[kt], bh0 + 2); mma16816(a3, qfrag[kt], bh1 + 2);
                    }
                }

                // --- decay weights (incl. 1/tau) + causal mask + rowsum ---
                const float ref2 = smf[eaF + 64];
                const float em_lo = exp2f(ref2 - m2_lo) * INV_TAU;
                const float em_hi = exp2f(ref2 - m2_hi) * INV_TAU;
                const bool diag = (ct >= 2 * rtc);
#pragma unroll
                for (int nt = 0; nt < 8; nt++) {
                    const int col0 = nt * 8 + 2 * qc;
                    const float w0 = smf[eaF + col0], w1 = smf[eaF + col0 + 1];
                    float* c = accS[nt];
                    float p00 = c[0] * w0 * em_lo, p01 = c[1] * w1 * em_lo;
                    float p10 = c[2] * w0 * em_hi, p11 = c[3] * w1 * em_hi;
                    if (diag) {
                        const int jc = j0 + col0;
                        if (jc > r_lo) p00 = 0.f;
                        if (jc + 1 > r_lo) p01 = 0.f;
                        if (jc > r_hi) p10 = 0.f;
                        if (jc + 1 > r_hi) p11 = 0.f;
                    }
                    bsl += p00 + p01;
                    bsh += p10 + p11;
                    c[0] = p00; c[1] = p01; c[2] = p10; c[3] = p11;
                }

                // --- GEMM2: O += P V (fp16, interleaved accumulators) ---
#pragma unroll
                for (int kt2 = 0; kt2 < 4; kt2++) {
                    const float* s0 = accS[2 * kt2];
                    const float* s1 = accS[2 * kt2 + 1];
                    uint32_t ph[4];
                    ph[0] = pack_hf2(s0[0], s0[1]);
                    ph[1] = pack_hf2(s0[2], s0[3]);
                    ph[2] = pack_hf2(s1[0], s1[1]);
                    ph[3] = pack_hf2(s1[2], s1[3]);
#pragma unroll
                    for (int dpp = 0; dpp < 4; dpp++) {
                        const uint32_t v0a = sb + kvb + V_IN_BUF + offV + kt2 * (16 * PITCH) + (2 * dpp) * 32;
                        const uint32_t v1a = v0a + 32;
                        uint32_t vh0[4], vh1[4];
                        ldsm4t(vh0, v0a);
                        ldsm4t(vh1, v1a);
                        float* o0 = accO[4 * dpp];
                        float* o1 = accO[4 * dpp + 1];
                        float* o2 = accO[4 * dpp + 2];
                        float* o3 = accO[4 * dpp + 3];
                        mma16816(o0, ph, vh0); mma16816(o2, ph, vh1);
                        mma16816(o1, ph, vh0 + 2); mma16816(o3, ph, vh1 + 2);
                    }
                }
            }
            __syncthreads();  // all reads of current buffer done before it is reused
        }

        // --- reduce rowsums across quad, store partials (fp16 O) ---
        bsl += __shfl_xor_sync(0xffffffffu, bsl, 1);
        bsl += __shfl_xor_sync(0xffffffffu, bsl, 2);
        bsh += __shfl_xor_sync(0xffffffffu, bsh, 1);
        bsh += __shfl_xor_sync(0xffffffffu, bsh, 2);
        if (qc == 0) {
            g_bpart[par][hb + r_lo] = bsl;
            g_bpart[par][hb + r_hi] = bsh;
        }
        __half* od = g_o16[par];
#pragma unroll
        for (int dt = 0; dt < 16; dt++) {
            const int col = h * HD + dt * 8 + 2 * qc;
            *reinterpret_cast<uint32_t*>(od + (size_t)r_lo * DIM + col) =
                pack_hf2(accO[dt][0], accO[dt][1]);
            *reinterpret_cast<uint32_t*>(od + (size_t)r_hi * DIM + col) =
                pack_hf2(accO[dt][2], accO[dt][3]);
        }
    }
}

// ---------------- merge + denominator + GroupNorm ----------------
__global__ void merge_gn(float* __restrict__ out, const float* __restrict__ gn_w,
                         const float* __restrict__ gn_b) {
    const int s = blockIdx.x;
    const int h = threadIdx.x >> 5;
    const int lane = threadIdx.x & 31;
    const size_t off = (size_t)s * DIM + h * HD + lane * 4;

    const uint2 ar = *reinterpret_cast<const uint2*>(g_o16[0] + off);
    const uint2 br = *reinterpret_cast<const uint2*>(g_o16[1] + off);
    const float2 a0 = __half22float2(*reinterpret_cast<const __half2*>(&ar.x));
    const float2 a1 = __half22float2(*reinterpret_cast<const __half2*>(&ar.y));
    const float2 b0 = __half22float2(*reinterpret_cast<const __half2*>(&br.x));
    const float2 b1 = __half22float2(*reinterpret_cast<const __half2*>(&br.y));

    const float bs = g_bpart[0][h * SEQ + s] + g_bpart[1][h * SEQ + s];
    const float inv = 1.0f / (fmaxf(fabsf(bs), g_nfloor[h * SEQ + s]) + 1e-6f);

    float4 x;
    x.x = (a0.x + b0.x) * inv;
    x.y = (a0.y + b0.y) * inv;
    x.z = (a1.x + b1.x) * inv;
    x.w = (a1.y + b1.y) * inv;

    float sum = x.x + x.y + x.z + x.w;
#pragma unroll
    for (int o = 16; o; o >>= 1) sum += __shfl_xor_sync(0xffffffffu, sum, o);
    const float mean = sum * (1.0f / 128.0f);
    const float d0 = x.x - mean, d1 = x.y - mean, d2 = x.z - mean, d3 = x.w - mean;
    float sq = d0 * d0 + d1 * d1 + d2 * d2 + d3 * d3;
#pragma unroll
    for (int o = 16; o; o >>= 1) sq += __shfl_xor_sync(0xffffffffu, sq, o);
    const float istd = rsqrtf(sq * (1.0f / 128.0f) + 1e-5f);

    const float4 w = *reinterpret_cast<const float4*>(gn_w + h * HD + lane * 4);
    const float4 bb = *reinterpret_cast<const float4*>(gn_b + h * HD + lane * 4);
    float4 y;
    y.x = d0 * istd * w.x + bb.x;
    y.y = d1 * istd * w.y + bb.y;
    y.z = d2 * istd * w.z + bb.z;
    y.w = d3 * istd * w.w + bb.w;
    *reinterpret_cast<float4*>(out + off) = y;
}

// ---------------- launch ----------------
extern "C" void kernel_launch(void* const* d_in, const int* in_sizes, int n_in,
                              void* d_out, int out_size) {
    const float* q = (const float*)d_in[0];
    const float* k = (const float*)d_in[1];
    const float* v = (const float*)d_in[2];
    const float* Wi_w = (const float*)d_in[3];
    const float* Wi_b = (const float*)d_in[4];
    const float* Wf_w = (const float*)d_in[5];
    const float* Wf_b = (const float*)d_in[6];
    const float* gn_w = (const float*)d_in[7];
    const float* gn_b = (const float*)d_in[8];
    float* out = (float*)d_out;

    gates_kernel<<<SEQ, 256>>>(q, k, v, Wi_w, Wi_b, Wf_w, Wf_b);
    scan_kernel<<<NHEADS, 256>>>();

    cudaFuncSetAttribute(mlstm_mma, cudaFuncAttributeMaxDynamicSharedMemorySize, SMEM_TOTAL);
    dim3 grid(16, NHEADS);
    mlstm_mma<<<grid, 256, SMEM_TOTAL>>>();

    merge_gn<<<SEQ, 256>>>(out, gn_w, gn_b);
}